// round 10
// baseline (speedup 1.0000x reference)
#include <cuda_runtime.h>
#include <math.h>
#include <stdint.h>

#define EPS 1e-5f
constexpr int NN   = 8192;
constexpr int IND  = 343;
constexpr int NPAD = 384;    // padded IND
constexpr int HIDD = 1000;
constexpr int HPAD = 1024;
constexpr int OUTD = 4;

// Scratch (allocation-free rule)
__device__ float g_featT[(size_t)NPAD * NN];  // feat^T, RNA, k-permuted, zero-padded
__device__ float g_Y[(size_t)NN * NPAD];      // adj @ feat
__device__ float g_W1T[(size_t)HPAD * NPAD];  // W1^T [n][k], RNA, k-permuted, zero-padded
__device__ float g_h1[(size_t)NN * HPAD];     // relu(Y @ W1 + b1)
__device__ float g_b1p[HPAD];

// ---------------------------------------------------------------------------
// helpers (base PTX only — sm_100 target has no tcgen05)
// ---------------------------------------------------------------------------
__device__ __forceinline__ uint32_t f2tf32(float v) {
    uint32_t r; asm("cvt.rna.tf32.f32 %0, %1;" : "=r"(r) : "f"(v)); return r;
}
__device__ __forceinline__ float rna_f(float v) { return __uint_as_float(f2tf32(v)); }

__device__ __forceinline__ void cp_async16(uint32_t dst, const void* src) {
    asm volatile("cp.async.cg.shared.global [%0], [%1], 16;\n" :: "r"(dst), "l"(src));
}
__device__ __forceinline__ void cp_commit() {
    asm volatile("cp.async.commit_group;\n" ::: "memory");
}
#define CP_WAIT(n) asm volatile("cp.async.wait_group %0;\n" :: "n"(n) : "memory")

__device__ __forceinline__ void mma_tf32(float* d, const uint32_t* a, const uint32_t* b) {
    asm volatile(
        "mma.sync.aligned.m16n8k8.row.col.f32.tf32.tf32.f32 "
        "{%0,%1,%2,%3}, {%4,%5,%6,%7}, {%8,%9}, {%0,%1,%2,%3};"
        : "+f"(d[0]), "+f"(d[1]), "+f"(d[2]), "+f"(d[3])
        : "r"(a[0]), "r"(a[1]), "r"(a[2]), "r"(a[3]), "r"(b[0]), "r"(b[1]));
}

// ---------------------------------------------------------------------------
// GEMM_A: Y[8192, 384] = adj @ featT^T   (tf32 HMMA)
// Tile 64m x 384n, 512 thr = 16 warps (4m x 4n), warp 16x96 (ni=12).
// 3-stage cp.async, one barrier per ktile. adj cvt.rna at frag load.
// grid = 128 CTAs, single wave.
// ---------------------------------------------------------------------------
constexpr int GA_LDA = 36;
constexpr int GA_LDB = 40;
constexpr int GA_ASTG = 64 * GA_LDA;            // 2304 floats
constexpr int GA_BSTG = NPAD * GA_LDB;          // 15360 floats
constexpr int GA_STG  = GA_ASTG + GA_BSTG;      // 17664 floats
constexpr int GA_SMEM = 3 * GA_STG * 4;         // 211968 B
constexpr int GA_KT   = NN / 32;                // 256

__global__ __launch_bounds__(512, 1)
void gemmA(const float* __restrict__ adj,
           const float* __restrict__ featT,
           float* __restrict__ Y)
{
    extern __shared__ float smf[];
    const uint32_t smb = (uint32_t)__cvta_generic_to_shared(smf);
    const int tid  = threadIdx.x;
    const int lane = tid & 31;
    const int wid  = tid >> 5;
    const int wm   = (wid & 3) * 16;
    const int wn   = (wid >> 2) * 96;
    const int r    = lane >> 2;
    const int c4   = lane & 3;
    const int m0   = blockIdx.x * 64;

    const float* Abase = adj + (size_t)m0 * NN;

    float acc[12][4];
    #pragma unroll
    for (int j = 0; j < 12; j++)
        #pragma unroll
        for (int q = 0; q < 4; q++) acc[j][q] = 0.f;

    const int arow = tid >> 3;                  // 0..63
    const int apos = tid & 7;                   // 0..7

    auto cpAB = [&](int kt, int s) {
        const uint32_t sa = smb + (uint32_t)(s * GA_STG) * 4;
        const uint32_t sb = sa + (uint32_t)GA_ASTG * 4;
        const float* Ak = Abase + kt * 32;
        const float* Bk = featT + kt * 32;
        cp_async16(sa + (uint32_t)(arow * GA_LDA + apos * 4) * 4,
                   Ak + (size_t)arow * NN + apos * 4);
        #pragma unroll
        for (int c = 0; c < 6; c++) {
            int row = arow + c * 64;
            cp_async16(sb + (uint32_t)(row * GA_LDB + apos * 4) * 4,
                       Bk + (size_t)row * NN + apos * 4);
        }
        cp_commit();
    };

    cpAB(0, 0);
    cpAB(1, 1);

    for (int kt = 0; kt < GA_KT; kt++) {
        if (kt + 1 < GA_KT) { CP_WAIT(1); } else { CP_WAIT(0); }
        __syncthreads();
        if (kt + 2 < GA_KT) cpAB(kt + 2, (kt + 2) % 3);

        const float* As = smf + (kt % 3) * GA_STG;
        const float* Bf = As + GA_ASTG;

        #pragma unroll
        for (int g = 0; g < 4; g++) {
            const int kk = g * 8;
            uint32_t a[4], b[12][2];
            {
                int base = (wm + r) * GA_LDA + kk + c4;
                a[0] = f2tf32(As[base]);
                a[1] = f2tf32(As[base + 8 * GA_LDA]);
                a[2] = f2tf32(As[base + 4]);
                a[3] = f2tf32(As[base + 8 * GA_LDA + 4]);
            }
            #pragma unroll
            for (int ni = 0; ni < 12; ni++) {
                float2 v = *(const float2*)(Bf + (wn + ni * 8 + r) * GA_LDB + kk + 2 * c4);
                b[ni][0] = __float_as_uint(v.x);
                b[ni][1] = __float_as_uint(v.y);
            }
            #pragma unroll
            for (int ni = 0; ni < 12; ni++)
                mma_tf32(acc[ni], a, b[ni]);
        }
    }

    #pragma unroll
    for (int h = 0; h < 2; h++) {
        int row = m0 + wm + r + h * 8;
        float* dst = Y + (size_t)row * NPAD + wn;
        #pragma unroll
        for (int ni = 0; ni < 12; ni++) {
            int col = ni * 8 + c4 * 2;
            float2 v;
            v.x = acc[ni][h * 2 + 0];
            v.y = acc[ni][h * 2 + 1];
            *(float2*)(dst + col) = v;
        }
    }
}

// ---------------------------------------------------------------------------
// GEMM_B: h1 = relu(Y @ W1 + b1)  [M=8192, N=1024(HPAD), K=384]
// R7 gemm2 structure: CTA 128m x 256n, 512 thr = 16 warps (4m x 4n),
// warp 32x64 (mi=2, ni=8). 3-stage cp.async, one barrier per ktile.
// A=Y (cvt.rna at frag load, lda=NPAD), B=W1T pre-rounded+permuted.
// K padding cols/rows are exact zeros -> no masking.
// ---------------------------------------------------------------------------
constexpr int GB_LDA = 36;
constexpr int GB_LDB = 40;
constexpr int GB_ASTG = 128 * GB_LDA;           // 4608 floats
constexpr int GB_BSTG = 256 * GB_LDB;           // 10240 floats
constexpr int GB_STG  = GB_ASTG + GB_BSTG;      // 14848
constexpr int GB_SMEM = 3 * GB_STG * 4;         // 178176 B
constexpr int GB_KT   = NPAD / 32;              // 12

__global__ __launch_bounds__(512, 1)
void gemmB(const float* __restrict__ Yb,
           const float* __restrict__ W1T,
           const float* __restrict__ bias,
           float* __restrict__ C)
{
    extern __shared__ float smf[];
    const uint32_t smb = (uint32_t)__cvta_generic_to_shared(smf);
    const int tid  = threadIdx.x;
    const int lane = tid & 31;
    const int wid  = tid >> 5;
    const int wm   = (wid & 3) * 32;
    const int wn   = (wid >> 2) * 64;
    const int r    = lane >> 2;
    const int c4   = lane & 3;
    const int m0   = blockIdx.y * 128;
    const int n0   = blockIdx.x * 256;

    const float* Abase = Yb  + (size_t)m0 * NPAD;
    const float* Bbase = W1T + (size_t)n0 * NPAD;

    float acc[2][8][4];
    #pragma unroll
    for (int i = 0; i < 2; i++)
        #pragma unroll
        for (int j = 0; j < 8; j++)
            #pragma unroll
            for (int q = 0; q < 4; q++) acc[i][j][q] = 0.f;

    const int row8 = tid >> 3, pos = tid & 7;

    auto cpAB = [&](int kt, int s) {
        const uint32_t sa = smb + (uint32_t)(s * GB_STG) * 4;
        const uint32_t sb = sa + (uint32_t)GB_ASTG * 4;
        const float* Ak = Abase + kt * 32;
        const float* Bk = Bbase + kt * 32;
        #pragma unroll
        for (int c = 0; c < 2; c++) {
            int row = row8 + c * 64;
            cp_async16(sa + (uint32_t)(row * GB_LDA + pos * 4) * 4,
                       Ak + (size_t)row * NPAD + pos * 4);
        }
        #pragma unroll
        for (int c = 0; c < 4; c++) {
            int row = row8 + c * 64;
            cp_async16(sb + (uint32_t)(row * GB_LDB + pos * 4) * 4,
                       Bk + (size_t)row * NPAD + pos * 4);
        }
        cp_commit();
    };

    cpAB(0, 0);
    cpAB(1, 1);

    for (int kt = 0; kt < GB_KT; kt++) {
        if (kt + 1 < GB_KT) { CP_WAIT(1); } else { CP_WAIT(0); }
        __syncthreads();
        if (kt + 2 < GB_KT) cpAB(kt + 2, (kt + 2) % 3);

        const float* As = smf + (kt % 3) * GB_STG;
        const float* Bf = As + GB_ASTG;

        #pragma unroll
        for (int g = 0; g < 4; g++) {
            const int kk = g * 8;
            uint32_t a[2][4], b[8][2];
            #pragma unroll
            for (int mi = 0; mi < 2; mi++) {
                int base = (wm + mi * 16 + r) * GB_LDA + kk + c4;
                a[mi][0] = f2tf32(As[base]);
                a[mi][1] = f2tf32(As[base + 8 * GB_LDA]);
                a[mi][2] = f2tf32(As[base + 4]);
                a[mi][3] = f2tf32(As[base + 8 * GB_LDA + 4]);
            }
            #pragma unroll
            for (int ni = 0; ni < 8; ni++) {
                float2 v = *(const float2*)(Bf + (wn + ni * 8 + r) * GB_LDB + kk + 2 * c4);
                b[ni][0] = __float_as_uint(v.x);
                b[ni][1] = __float_as_uint(v.y);
            }
            #pragma unroll
            for (int mi = 0; mi < 2; mi++)
                #pragma unroll
                for (int ni = 0; ni < 8; ni++)
                    mma_tf32(acc[mi][ni], a[mi], b[ni]);
        }
    }

    #pragma unroll
    for (int mi = 0; mi < 2; mi++) {
        #pragma unroll
        for (int h = 0; h < 2; h++) {
            int row = m0 + wm + mi * 16 + r + h * 8;
            float* dst = C + (size_t)row * HPAD + n0 + wn;
            #pragma unroll
            for (int ni = 0; ni < 8; ni++) {
                int col = ni * 8 + c4 * 2;
                float2 v;
                v.x = fmaxf(acc[mi][ni][h * 2 + 0] + bias[n0 + wn + col],     0.f);
                v.y = fmaxf(acc[mi][ni][h * 2 + 1] + bias[n0 + wn + col + 1], 0.f);
                *(float2*)(dst + col) = v;
            }
        }
    }
}

// ---------------------------------------------------------------------------
// transpose feat [8192, 343] -> featT [384, 8192], RNA, k-permuted, padded.
// ---------------------------------------------------------------------------
__global__ void transpose_feat(const float* __restrict__ in,
                               float* __restrict__ out)
{
    __shared__ float t[32][33];
    int x  = blockIdx.x * 32 + threadIdx.x;   // n (0..383)
    int y0 = blockIdx.y * 32;                 // k base
    #pragma unroll
    for (int j = threadIdx.y; j < 32; j += 8)
        t[j][threadIdx.x] = (x < IND) ? in[(size_t)(y0 + j) * IND + x] : 0.f;
    __syncthreads();
    int k  = y0 + threadIdx.x;
    int o  = k & 7;
    int kp = (k & ~7) | ((o < 4) ? (2 * o) : (2 * (o - 4) + 1));
    int n0 = blockIdx.x * 32;
    #pragma unroll
    for (int j = threadIdx.y; j < 32; j += 8)
        out[(size_t)(n0 + j) * NN + kp] = rna_f(t[threadIdx.x][j]);
}

// ---------------------------------------------------------------------------
// transpose W1 [343, 1000] -> W1T [1024, 384], RNA, k-permuted, padded.
// ---------------------------------------------------------------------------
__global__ void transpose_w1(const float* __restrict__ in,
                             float* __restrict__ out)
{
    __shared__ float t[32][33];
    int x  = blockIdx.x * 32 + threadIdx.x;   // n (0..1023)
    int y0 = blockIdx.y * 32;                 // k base (0..383)
    #pragma unroll
    for (int j = threadIdx.y; j < 32; j += 8) {
        int k = y0 + j;
        t[j][threadIdx.x] = (x < HIDD && k < IND) ? in[(size_t)k * HIDD + x] : 0.f;
    }
    __syncthreads();
    int k  = y0 + threadIdx.x;
    int o  = k & 7;
    int kp = (k & ~7) | ((o < 4) ? (2 * o) : (2 * (o - 4) + 1));
    int n0 = blockIdx.x * 32;
    #pragma unroll
    for (int j = threadIdx.y; j < 32; j += 8)
        out[(size_t)(n0 + j) * NPAD + kp] = rna_f(t[threadIdx.x][j]);
}

__global__ void pad_bias_kernel(const float* __restrict__ b1, float* __restrict__ b1p) {
    int i = threadIdx.x;
    b1p[i] = (i < HIDD) ? b1[i] : 0.f;
}

// ---------------------------------------------------------------------------
// LayerNorm(1000) + head, one warp per row, float4 loads.
// HIDD = 1000 = 250 float4s exactly.
// ---------------------------------------------------------------------------
__global__ __launch_bounds__(256)
void ln_head_kernel(const float* __restrict__ h,
                    const float* __restrict__ gamma,
                    const float* __restrict__ beta,
                    const float* __restrict__ Wm,
                    const float* __restrict__ bm,
                    float* __restrict__ out)
{
    const int row  = blockIdx.x * 8 + threadIdx.y;
    const int lane = threadIdx.x;
    const float4* hr = (const float4*)(h + (size_t)row * HPAD);
    const float4* g4 = (const float4*)gamma;
    const float4* be4 = (const float4*)beta;
    const float4* wm4 = (const float4*)Wm;     // row n of Wm is one float4

    float4 v[8];
    float s = 0.f, ss = 0.f;
    #pragma unroll
    for (int i = 0; i < 8; i++) {
        int idx = lane + 32 * i;               // float4 index, 250 valid
        float4 x = (idx < 250) ? hr[idx] : make_float4(0.f, 0.f, 0.f, 0.f);
        v[i] = x;
        s  += x.x + x.y + x.z + x.w;
        ss += x.x * x.x + x.y * x.y + x.z * x.z + x.w * x.w;
    }
    #pragma unroll
    for (int off = 16; off > 0; off >>= 1) {
        s  += __shfl_xor_sync(0xFFFFFFFF, s,  off);
        ss += __shfl_xor_sync(0xFFFFFFFF, ss, off);
    }
    const float mu   = s * (1.0f / HIDD);
    const float var  = ss * (1.0f / HIDD) - mu * mu;
    const float rinv = rsqrtf(var + EPS);

    float4 acc = make_float4(0.f, 0.f, 0.f, 0.f);
    #pragma unroll
    for (int i = 0; i < 8; i++) {
        int idx = lane + 32 * i;
        if (idx < 250) {
            float4 g = g4[idx], be = be4[idx];
            float xn0 = (v[i].x - mu) * rinv * g.x + be.x;
            float xn1 = (v[i].y - mu) * rinv * g.y + be.y;
            float xn2 = (v[i].z - mu) * rinv * g.z + be.z;
            float xn3 = (v[i].w - mu) * rinv * g.w + be.w;
            float4 w0 = wm4[idx * 4 + 0];
            float4 w1 = wm4[idx * 4 + 1];
            float4 w2 = wm4[idx * 4 + 2];
            float4 w3 = wm4[idx * 4 + 3];
            acc.x = fmaf(xn0, w0.x, fmaf(xn1, w1.x, fmaf(xn2, w2.x, fmaf(xn3, w3.x, acc.x))));
            acc.y = fmaf(xn0, w0.y, fmaf(xn1, w1.y, fmaf(xn2, w2.y, fmaf(xn3, w3.y, acc.y))));
            acc.z = fmaf(xn0, w0.z, fmaf(xn1, w1.z, fmaf(xn2, w2.z, fmaf(xn3, w3.z, acc.z))));
            acc.w = fmaf(xn0, w0.w, fmaf(xn1, w1.w, fmaf(xn2, w2.w, fmaf(xn3, w3.w, acc.w))));
        }
    }
    #pragma unroll
    for (int off = 16; off > 0; off >>= 1) {
        acc.x += __shfl_xor_sync(0xFFFFFFFF, acc.x, off);
        acc.y += __shfl_xor_sync(0xFFFFFFFF, acc.y, off);
        acc.z += __shfl_xor_sync(0xFFFFFFFF, acc.z, off);
        acc.w += __shfl_xor_sync(0xFFFFFFFF, acc.w, off);
    }
    if (lane == 0) {
        float4 b = *(const float4*)bm;
        float4 o;
        o.x = acc.x + b.x; o.y = acc.y + b.y;
        o.z = acc.z + b.z; o.w = acc.w + b.w;
        *(float4*)(out + (size_t)row * OUTD) = o;
    }
}

// ---------------------------------------------------------------------------
extern "C" void kernel_launch(void* const* d_in, const int* in_sizes, int n_in,
                              void* d_out, int out_size)
{
    const float* adj   = (const float*)d_in[0];
    const float* feat  = (const float*)d_in[1];
    const float* W1    = (const float*)d_in[2];
    const float* b1    = (const float*)d_in[3];
    const float* gamma = (const float*)d_in[4];
    const float* beta  = (const float*)d_in[5];
    const float* Wm    = (const float*)d_in[6];
    const float* bm    = (const float*)d_in[7];
    float* out = (float*)d_out;

    float *featT, *Yb, *W1T, *h1, *b1p;
    cudaGetSymbolAddress((void**)&featT, g_featT);
    cudaGetSymbolAddress((void**)&Yb,    g_Y);
    cudaGetSymbolAddress((void**)&W1T,   g_W1T);
    cudaGetSymbolAddress((void**)&h1,    g_h1);
    cudaGetSymbolAddress((void**)&b1p,   g_b1p);

    cudaFuncSetAttribute(gemmA, cudaFuncAttributeMaxDynamicSharedMemorySize, GA_SMEM);
    cudaFuncSetAttribute(gemmB, cudaFuncAttributeMaxDynamicSharedMemorySize, GB_SMEM);

    // prep: featT, W1T, padded bias
    {
        dim3 block(32, 8);
        dim3 gridF(NPAD / 32, NN / 32);
        transpose_feat<<<gridF, block>>>(feat, featT);
        dim3 gridW(HPAD / 32, NPAD / 32);
        transpose_w1<<<gridW, block>>>(W1, W1T);
        pad_bias_kernel<<<1, HPAD>>>(b1, b1p);
    }

    // GEMM_A: Y = adj @ feat   (128 CTAs, single wave)
    gemmA<<<NN / 64, 512, GA_SMEM>>>(adj, featT, Yb);

    // GEMM_B: h1 = relu(Y @ W1 + b1)
    {
        dim3 grid(HPAD / 256, NN / 128);
        gemmB<<<grid, 512, GB_SMEM>>>(Yb, W1T, b1p, h1);
    }

    // LayerNorm + head
    {
        dim3 block(32, 8);
        ln_head_kernel<<<NN / 8, block>>>(h1, gamma, beta, Wm, bm, out);
    }
}

// round 12
// speedup vs baseline: 1.0350x; 1.0350x over previous
#include <cuda_runtime.h>
#include <math.h>
#include <stdint.h>

#define EPS 1e-5f
constexpr int NN   = 8192;
constexpr int IND  = 343;
constexpr int NPAD = 384;    // padded IND
constexpr int HIDD = 1000;
constexpr int HPAD = 1024;
constexpr int OUTD = 4;

// Scratch (allocation-free rule)
__device__ float g_featT[(size_t)NPAD * NN];  // feat^T, RNA, k-permuted, zero-padded
__device__ float g_Y[(size_t)NN * NPAD];      // adj @ feat
__device__ float g_W1T[(size_t)HPAD * NPAD];  // W1^T [n][k], RNA, k-permuted, zero-padded
__device__ float g_h1[(size_t)NN * HPAD];     // relu(Y @ W1 + b1)
__device__ float g_b1p[HPAD];

// ---------------------------------------------------------------------------
// helpers (base PTX only — sm_100 target has no tcgen05)
// ---------------------------------------------------------------------------
__device__ __forceinline__ uint32_t f2tf32(float v) {
    uint32_t r; asm("cvt.rna.tf32.f32 %0, %1;" : "=r"(r) : "f"(v)); return r;
}
__device__ __forceinline__ float rna_f(float v) { return __uint_as_float(f2tf32(v)); }

__device__ __forceinline__ void cp_async16(uint32_t dst, const void* src) {
    asm volatile("cp.async.cg.shared.global [%0], [%1], 16;\n" :: "r"(dst), "l"(src));
}
__device__ __forceinline__ void cp_commit() {
    asm volatile("cp.async.commit_group;\n" ::: "memory");
}
#define CP_WAIT(n) asm volatile("cp.async.wait_group %0;\n" :: "n"(n) : "memory")

__device__ __forceinline__ void mma_tf32(float* d, const uint32_t* a, const uint32_t* b) {
    asm volatile(
        "mma.sync.aligned.m16n8k8.row.col.f32.tf32.tf32.f32 "
        "{%0,%1,%2,%3}, {%4,%5,%6,%7}, {%8,%9}, {%0,%1,%2,%3};"
        : "+f"(d[0]), "+f"(d[1]), "+f"(d[2]), "+f"(d[3])
        : "r"(a[0]), "r"(a[1]), "r"(a[2]), "r"(a[3]), "r"(b[0]), "r"(b[1]));
}

// ---------------------------------------------------------------------------
// GEMM_A: Y[8192, 384] = adj @ featT^T   (tf32 HMMA)  — R8 proven config
// Tile 64m x 384n, 512 thr = 16 warps (4m x 4n), warp 16x96 (ni=12).
// 2-stage cp.async double buffer, one barrier per ktile.
// adj cvt.rna at frag load. grid = 128 CTAs, single wave.
// ---------------------------------------------------------------------------
constexpr int GA_LDA = 36;
constexpr int GA_LDB = 40;
constexpr int GA_ASTG = 64 * GA_LDA;            // 2304 floats
constexpr int GA_BSTG = NPAD * GA_LDB;          // 15360 floats
constexpr int GA_STG  = GA_ASTG + GA_BSTG;      // 17664 floats
constexpr int GA_SMEM = 2 * GA_STG * 4;         // 141312 B
constexpr int GA_KT   = NN / 32;                // 256

__global__ __launch_bounds__(512, 1)
void gemmA(const float* __restrict__ adj,
           const float* __restrict__ featT,
           float* __restrict__ Y)
{
    extern __shared__ float smf[];
    const uint32_t smb = (uint32_t)__cvta_generic_to_shared(smf);
    const int tid  = threadIdx.x;
    const int lane = tid & 31;
    const int wid  = tid >> 5;
    const int wm   = (wid & 3) * 16;
    const int wn   = (wid >> 2) * 96;
    const int r    = lane >> 2;
    const int c4   = lane & 3;
    const int m0   = blockIdx.x * 64;

    const float* Abase = adj + (size_t)m0 * NN;

    float acc[12][4];
    #pragma unroll
    for (int j = 0; j < 12; j++)
        #pragma unroll
        for (int q = 0; q < 4; q++) acc[j][q] = 0.f;

    const int arow = tid >> 3;                  // 0..63
    const int apos = tid & 7;                   // 0..7

    auto cpAB = [&](int kt, int s) {
        const uint32_t sa = smb + (uint32_t)(s * GA_STG) * 4;
        const uint32_t sb = sa + (uint32_t)GA_ASTG * 4;
        const float* Ak = Abase + kt * 32;
        const float* Bk = featT + kt * 32;
        cp_async16(sa + (uint32_t)(arow * GA_LDA + apos * 4) * 4,
                   Ak + (size_t)arow * NN + apos * 4);
        #pragma unroll
        for (int c = 0; c < 6; c++) {
            int row = arow + c * 64;
            cp_async16(sb + (uint32_t)(row * GA_LDB + apos * 4) * 4,
                       Bk + (size_t)row * NN + apos * 4);
        }
        cp_commit();
    };

    cpAB(0, 0);

    for (int kt = 0; kt < GA_KT; kt++) {
        CP_WAIT(0);
        __syncthreads();
        if (kt + 1 < GA_KT) cpAB(kt + 1, (kt + 1) & 1);

        const float* As = smf + (kt & 1) * GA_STG;
        const float* Bf = As + GA_ASTG;

        #pragma unroll
        for (int g = 0; g < 4; g++) {
            const int kk = g * 8;
            uint32_t a[4], b[12][2];
            {
                int base = (wm + r) * GA_LDA + kk + c4;
                a[0] = f2tf32(As[base]);
                a[1] = f2tf32(As[base + 8 * GA_LDA]);
                a[2] = f2tf32(As[base + 4]);
                a[3] = f2tf32(As[base + 8 * GA_LDA + 4]);
            }
            #pragma unroll
            for (int ni = 0; ni < 12; ni++) {
                float2 v = *(const float2*)(Bf + (wn + ni * 8 + r) * GA_LDB + kk + 2 * c4);
                b[ni][0] = __float_as_uint(v.x);
                b[ni][1] = __float_as_uint(v.y);
            }
            #pragma unroll
            for (int ni = 0; ni < 12; ni++)
                mma_tf32(acc[ni], a, b[ni]);
        }
    }

    #pragma unroll
    for (int h = 0; h < 2; h++) {
        int row = m0 + wm + r + h * 8;
        float* dst = Y + (size_t)row * NPAD + wn;
        #pragma unroll
        for (int ni = 0; ni < 12; ni++) {
            int col = ni * 8 + c4 * 2;
            float2 v;
            v.x = acc[ni][h * 2 + 0];
            v.y = acc[ni][h * 2 + 1];
            *(float2*)(dst + col) = v;
        }
    }
}

// ---------------------------------------------------------------------------
// GEMM_B: h1 = relu(Y @ W1 + b1)  [M=8192, N=1024(HPAD), K=384]
// CTA 128m x 256n, 512 thr = 16 warps (4m x 4n), warp 32x64 (mi=2, ni=8).
// 3-stage cp.async, one barrier per ktile. A=Y (cvt.rna at frag load),
// B=W1T pre-rounded+permuted. K padding is exact zeros -> no masking.
// ---------------------------------------------------------------------------
constexpr int GB_LDA = 36;
constexpr int GB_LDB = 40;
constexpr int GB_ASTG = 128 * GB_LDA;           // 4608 floats
constexpr int GB_BSTG = 256 * GB_LDB;           // 10240 floats
constexpr int GB_STG  = GB_ASTG + GB_BSTG;      // 14848
constexpr int GB_SMEM = 3 * GB_STG * 4;         // 178176 B
constexpr int GB_KT   = NPAD / 32;              // 12

__global__ __launch_bounds__(512, 1)
void gemmB(const float* __restrict__ Yb,
           const float* __restrict__ W1T,
           const float* __restrict__ bias,
           float* __restrict__ C)
{
    extern __shared__ float smf[];
    const uint32_t smb = (uint32_t)__cvta_generic_to_shared(smf);
    const int tid  = threadIdx.x;
    const int lane = tid & 31;
    const int wid  = tid >> 5;
    const int wm   = (wid & 3) * 32;
    const int wn   = (wid >> 2) * 64;
    const int r    = lane >> 2;
    const int c4   = lane & 3;
    const int m0   = blockIdx.y * 128;
    const int n0   = blockIdx.x * 256;

    const float* Abase = Yb  + (size_t)m0 * NPAD;
    const float* Bbase = W1T + (size_t)n0 * NPAD;

    float acc[2][8][4];
    #pragma unroll
    for (int i = 0; i < 2; i++)
        #pragma unroll
        for (int j = 0; j < 8; j++)
            #pragma unroll
            for (int q = 0; q < 4; q++) acc[i][j][q] = 0.f;

    const int row8 = tid >> 3, pos = tid & 7;

    auto cpAB = [&](int kt, int s) {
        const uint32_t sa = smb + (uint32_t)(s * GB_STG) * 4;
        const uint32_t sb = sa + (uint32_t)GB_ASTG * 4;
        const float* Ak = Abase + kt * 32;
        const float* Bk = Bbase + kt * 32;
        #pragma unroll
        for (int c = 0; c < 2; c++) {
            int row = row8 + c * 64;
            cp_async16(sa + (uint32_t)(row * GB_LDA + pos * 4) * 4,
                       Ak + (size_t)row * NPAD + pos * 4);
        }
        #pragma unroll
        for (int c = 0; c < 4; c++) {
            int row = row8 + c * 64;
            cp_async16(sb + (uint32_t)(row * GB_LDB + pos * 4) * 4,
                       Bk + (size_t)row * NPAD + pos * 4);
        }
        cp_commit();
    };

    cpAB(0, 0);
    cpAB(1, 1);

    for (int kt = 0; kt < GB_KT; kt++) {
        if (kt + 1 < GB_KT) { CP_WAIT(1); } else { CP_WAIT(0); }
        __syncthreads();
        if (kt + 2 < GB_KT) cpAB(kt + 2, (kt + 2) % 3);

        const float* As = smf + (kt % 3) * GB_STG;
        const float* Bf = As + GB_ASTG;

        #pragma unroll
        for (int g = 0; g < 4; g++) {
            const int kk = g * 8;
            uint32_t a[2][4], b[8][2];
            #pragma unroll
            for (int mi = 0; mi < 2; mi++) {
                int base = (wm + mi * 16 + r) * GB_LDA + kk + c4;
                a[mi][0] = f2tf32(As[base]);
                a[mi][1] = f2tf32(As[base + 8 * GB_LDA]);
                a[mi][2] = f2tf32(As[base + 4]);
                a[mi][3] = f2tf32(As[base + 8 * GB_LDA + 4]);
            }
            #pragma unroll
            for (int ni = 0; ni < 8; ni++) {
                float2 v = *(const float2*)(Bf + (wn + ni * 8 + r) * GB_LDB + kk + 2 * c4);
                b[ni][0] = __float_as_uint(v.x);
                b[ni][1] = __float_as_uint(v.y);
            }
            #pragma unroll
            for (int mi = 0; mi < 2; mi++)
                #pragma unroll
                for (int ni = 0; ni < 8; ni++)
                    mma_tf32(acc[mi][ni], a[mi], b[ni]);
        }
    }

    #pragma unroll
    for (int mi = 0; mi < 2; mi++) {
        #pragma unroll
        for (int h = 0; h < 2; h++) {
            int row = m0 + wm + mi * 16 + r + h * 8;
            float* dst = C + (size_t)row * HPAD + n0 + wn;
            #pragma unroll
            for (int ni = 0; ni < 8; ni++) {
                int col = ni * 8 + c4 * 2;
                float2 v;
                v.x = fmaxf(acc[mi][ni][h * 2 + 0] + bias[n0 + wn + col],     0.f);
                v.y = fmaxf(acc[mi][ni][h * 2 + 1] + bias[n0 + wn + col + 1], 0.f);
                *(float2*)(dst + col) = v;
            }
        }
    }
}

// ---------------------------------------------------------------------------
// transpose feat [8192, 343] -> featT [384, 8192], RNA, k-permuted, padded.
// ---------------------------------------------------------------------------
__global__ void transpose_feat(const float* __restrict__ in,
                               float* __restrict__ out)
{
    __shared__ float t[32][33];
    int x  = blockIdx.x * 32 + threadIdx.x;   // n (0..383)
    int y0 = blockIdx.y * 32;                 // k base
    #pragma unroll
    for (int j = threadIdx.y; j < 32; j += 8)
        t[j][threadIdx.x] = (x < IND) ? in[(size_t)(y0 + j) * IND + x] : 0.f;
    __syncthreads();
    int k  = y0 + threadIdx.x;
    int o  = k & 7;
    int kp = (k & ~7) | ((o < 4) ? (2 * o) : (2 * (o - 4) + 1));
    int n0 = blockIdx.x * 32;
    #pragma unroll
    for (int j = threadIdx.y; j < 32; j += 8)
        out[(size_t)(n0 + j) * NN + kp] = rna_f(t[threadIdx.x][j]);
}

// ---------------------------------------------------------------------------
// transpose W1 [343, 1000] -> W1T [1024, 384], RNA, k-permuted, padded.
// ---------------------------------------------------------------------------
__global__ void transpose_w1(const float* __restrict__ in,
                             float* __restrict__ out)
{
    __shared__ float t[32][33];
    int x  = blockIdx.x * 32 + threadIdx.x;   // n (0..1023)
    int y0 = blockIdx.y * 32;                 // k base (0..383)
    #pragma unroll
    for (int j = threadIdx.y; j < 32; j += 8) {
        int k = y0 + j;
        t[j][threadIdx.x] = (x < HIDD && k < IND) ? in[(size_t)k * HIDD + x] : 0.f;
    }
    __syncthreads();
    int k  = y0 + threadIdx.x;
    int o  = k & 7;
    int kp = (k & ~7) | ((o < 4) ? (2 * o) : (2 * (o - 4) + 1));
    int n0 = blockIdx.x * 32;
    #pragma unroll
    for (int j = threadIdx.y; j < 32; j += 8)
        out[(size_t)(n0 + j) * NPAD + kp] = rna_f(t[threadIdx.x][j]);
}

__global__ void pad_bias_kernel(const float* __restrict__ b1, float* __restrict__ b1p) {
    int i = threadIdx.x;
    b1p[i] = (i < HIDD) ? b1[i] : 0.f;
}

// ---------------------------------------------------------------------------
// LayerNorm(1000) + head, one warp per row, float4 loads.
// ---------------------------------------------------------------------------
__global__ __launch_bounds__(256)
void ln_head_kernel(const float* __restrict__ h,
                    const float* __restrict__ gamma,
                    const float* __restrict__ beta,
                    const float* __restrict__ Wm,
                    const float* __restrict__ bm,
                    float* __restrict__ out)
{
    const int row  = blockIdx.x * 8 + threadIdx.y;
    const int lane = threadIdx.x;
    const float4* hr = (const float4*)(h + (size_t)row * HPAD);
    const float4* g4 = (const float4*)gamma;
    const float4* be4 = (const float4*)beta;
    const float4* wm4 = (const float4*)Wm;     // row n of Wm is one float4

    float4 v[8];
    float s = 0.f, ss = 0.f;
    #pragma unroll
    for (int i = 0; i < 8; i++) {
        int idx = lane + 32 * i;               // float4 index, 250 valid
        float4 x = (idx < 250) ? hr[idx] : make_float4(0.f, 0.f, 0.f, 0.f);
        v[i] = x;
        s  += x.x + x.y + x.z + x.w;
        ss += x.x * x.x + x.y * x.y + x.z * x.z + x.w * x.w;
    }
    #pragma unroll
    for (int off = 16; off > 0; off >>= 1) {
        s  += __shfl_xor_sync(0xFFFFFFFF, s,  off);
        ss += __shfl_xor_sync(0xFFFFFFFF, ss, off);
    }
    const float mu   = s * (1.0f / HIDD);
    const float var  = ss * (1.0f / HIDD) - mu * mu;
    const float rinv = rsqrtf(var + EPS);

    float4 acc = make_float4(0.f, 0.f, 0.f, 0.f);
    #pragma unroll
    for (int i = 0; i < 8; i++) {
        int idx = lane + 32 * i;
        if (idx < 250) {
            float4 g = g4[idx], be = be4[idx];
            float xn0 = (v[i].x - mu) * rinv * g.x + be.x;
            float xn1 = (v[i].y - mu) * rinv * g.y + be.y;
            float xn2 = (v[i].z - mu) * rinv * g.z + be.z;
            float xn3 = (v[i].w - mu) * rinv * g.w + be.w;
            float4 w0 = wm4[idx * 4 + 0];
            float4 w1 = wm4[idx * 4 + 1];
            float4 w2 = wm4[idx * 4 + 2];
            float4 w3 = wm4[idx * 4 + 3];
            acc.x = fmaf(xn0, w0.x, fmaf(xn1, w1.x, fmaf(xn2, w2.x, fmaf(xn3, w3.x, acc.x))));
            acc.y = fmaf(xn0, w0.y, fmaf(xn1, w1.y, fmaf(xn2, w2.y, fmaf(xn3, w3.y, acc.y))));
            acc.z = fmaf(xn0, w0.z, fmaf(xn1, w1.z, fmaf(xn2, w2.z, fmaf(xn3, w3.z, acc.z))));
            acc.w = fmaf(xn0, w0.w, fmaf(xn1, w1.w, fmaf(xn2, w2.w, fmaf(xn3, w3.w, acc.w))));
        }
    }
    #pragma unroll
    for (int off = 16; off > 0; off >>= 1) {
        acc.x += __shfl_xor_sync(0xFFFFFFFF, acc.x, off);
        acc.y += __shfl_xor_sync(0xFFFFFFFF, acc.y, off);
        acc.z += __shfl_xor_sync(0xFFFFFFFF, acc.z, off);
        acc.w += __shfl_xor_sync(0xFFFFFFFF, acc.w, off);
    }
    if (lane == 0) {
        float4 b = *(const float4*)bm;
        float4 o;
        o.x = acc.x + b.x; o.y = acc.y + b.y;
        o.z = acc.z + b.z; o.w = acc.w + b.w;
        *(float4*)(out + (size_t)row * OUTD) = o;
    }
}

// ---------------------------------------------------------------------------
extern "C" void kernel_launch(void* const* d_in, const int* in_sizes, int n_in,
                              void* d_out, int out_size)
{
    const float* adj   = (const float*)d_in[0];
    const float* feat  = (const float*)d_in[1];
    const float* W1    = (const float*)d_in[2];
    const float* b1    = (const float*)d_in[3];
    const float* gamma = (const float*)d_in[4];
    const float* beta  = (const float*)d_in[5];
    const float* Wm    = (const float*)d_in[6];
    const float* bm    = (const float*)d_in[7];
    float* out = (float*)d_out;

    float *featT, *Yb, *W1T, *h1, *b1p;
    cudaGetSymbolAddress((void**)&featT, g_featT);
    cudaGetSymbolAddress((void**)&Yb,    g_Y);
    cudaGetSymbolAddress((void**)&W1T,   g_W1T);
    cudaGetSymbolAddress((void**)&h1,    g_h1);
    cudaGetSymbolAddress((void**)&b1p,   g_b1p);

    cudaFuncSetAttribute(gemmA, cudaFuncAttributeMaxDynamicSharedMemorySize, GA_SMEM);
    cudaFuncSetAttribute(gemmB, cudaFuncAttributeMaxDynamicSharedMemorySize, GB_SMEM);

    // prep: featT, W1T, padded bias
    {
        dim3 block(32, 8);
        dim3 gridF(NPAD / 32, NN / 32);
        transpose_feat<<<gridF, block>>>(feat, featT);
        dim3 gridW(HPAD / 32, NPAD / 32);
        transpose_w1<<<gridW, block>>>(W1, W1T);
        pad_bias_kernel<<<1, HPAD>>>(b1, b1p);
    }

    // GEMM_A: Y = adj @ feat   (128 CTAs, single wave)
    gemmA<<<NN / 64, 512, GA_SMEM>>>(adj, featT, Yb);

    // GEMM_B: h1 = relu(Y @ W1 + b1)
    {
        dim3 grid(HPAD / 256, NN / 128);
        gemmB<<<grid, 512, GB_SMEM>>>(Yb, W1T, b1p, h1);
    }

    // LayerNorm + head
    {
        dim3 block(32, 8);
        ln_head_kernel<<<NN / 8, block>>>(h1, gamma, beta, Wm, bm, out);
    }
}

// round 13
// speedup vs baseline: 1.0591x; 1.0232x over previous
#include <cuda_runtime.h>
#include <math.h>
#include <stdint.h>

#define EPS 1e-5f
constexpr int NN   = 8192;
constexpr int IND  = 343;
constexpr int NPAD = 384;    // padded IND
constexpr int HIDD = 1000;
constexpr int HPAD = 1024;
constexpr int OUTD = 4;
constexpr int KSPLIT = 8;    // gemmA split-K factor

// Scratch (allocation-free rule)
__device__ float g_featT[(size_t)NPAD * NN];            // feat^T, RNA, k-permuted, padded
__device__ float g_Ypart[(size_t)KSPLIT * NN * NPAD];   // split-K partials (100 MB)
__device__ float g_Y[(size_t)NN * NPAD];                // adj @ feat
__device__ float g_W1T[(size_t)HPAD * NPAD];            // W1^T, RNA, k-permuted, padded
__device__ float g_h1[(size_t)NN * HPAD];               // relu(Y @ W1 + b1)
__device__ float g_b1p[HPAD];

// ---------------------------------------------------------------------------
// helpers (base PTX only — sm_100 target has no tcgen05)
// ---------------------------------------------------------------------------
__device__ __forceinline__ uint32_t f2tf32(float v) {
    uint32_t r; asm("cvt.rna.tf32.f32 %0, %1;" : "=r"(r) : "f"(v)); return r;
}
__device__ __forceinline__ float rna_f(float v) { return __uint_as_float(f2tf32(v)); }

__device__ __forceinline__ void cp_async16(uint32_t dst, const void* src) {
    asm volatile("cp.async.cg.shared.global [%0], [%1], 16;\n" :: "r"(dst), "l"(src));
}
__device__ __forceinline__ void cp_commit() {
    asm volatile("cp.async.commit_group;\n" ::: "memory");
}
#define CP_WAIT(n) asm volatile("cp.async.wait_group %0;\n" :: "n"(n) : "memory")

__device__ __forceinline__ void mma_tf32(float* d, const uint32_t* a, const uint32_t* b) {
    asm volatile(
        "mma.sync.aligned.m16n8k8.row.col.f32.tf32.tf32.f32 "
        "{%0,%1,%2,%3}, {%4,%5,%6,%7}, {%8,%9}, {%0,%1,%2,%3};"
        : "+f"(d[0]), "+f"(d[1]), "+f"(d[2]), "+f"(d[3])
        : "r"(a[0]), "r"(a[1]), "r"(a[2]), "r"(a[3]), "r"(b[0]), "r"(b[1]));
}

// ---------------------------------------------------------------------------
// GEMM_A (split-K8): Ypart[ks] += adj[:, ks*1024:(ks+1)*1024] @ featT-slice^T
// Per CTA: proven 64m x 384n tile, 512 thr (16 warps, 4m x 4n, warp 16x96),
// 2-stage cp.async, one barrier per ktile, 32 ktiles (K=1024).
// grid = (128 m-tiles, 8 k-slices) = 1024 CTAs -> ceil(1024/148)=7 unit-waves.
// ---------------------------------------------------------------------------
constexpr int GA_LDA = 36;
constexpr int GA_LDB = 40;
constexpr int GA_ASTG = 64 * GA_LDA;            // 2304 floats
constexpr int GA_BSTG = NPAD * GA_LDB;          // 15360 floats
constexpr int GA_STG  = GA_ASTG + GA_BSTG;      // 17664 floats
constexpr int GA_SMEM = 2 * GA_STG * 4;         // 141312 B
constexpr int GA_KSLC = NN / KSPLIT;            // 1024 K per slice
constexpr int GA_KT   = GA_KSLC / 32;           // 32 ktiles per CTA

__global__ __launch_bounds__(512, 1)
void gemmA_split(const float* __restrict__ adj,
                 const float* __restrict__ featT,
                 float* __restrict__ Ypart)
{
    extern __shared__ float smf[];
    const uint32_t smb = (uint32_t)__cvta_generic_to_shared(smf);
    const int tid  = threadIdx.x;
    const int lane = tid & 31;
    const int wid  = tid >> 5;
    const int wm   = (wid & 3) * 16;
    const int wn   = (wid >> 2) * 96;
    const int r    = lane >> 2;
    const int c4   = lane & 3;
    const int m0   = blockIdx.x * 64;
    const int ks   = blockIdx.y;                 // k-slice 0..7
    const int kofs = ks * GA_KSLC;               // k offset (multiple of 1024)

    const float* Abase = adj   + (size_t)m0 * NN + kofs;
    const float* Bbase = featT + kofs;
    float* Ydst = Ypart + (size_t)ks * NN * NPAD;

    float acc[12][4];
    #pragma unroll
    for (int j = 0; j < 12; j++)
        #pragma unroll
        for (int q = 0; q < 4; q++) acc[j][q] = 0.f;

    const int arow = tid >> 3;                  // 0..63
    const int apos = tid & 7;                   // 0..7

    auto cpAB = [&](int kt, int s) {
        const uint32_t sa = smb + (uint32_t)(s * GA_STG) * 4;
        const uint32_t sb = sa + (uint32_t)GA_ASTG * 4;
        const float* Ak = Abase + kt * 32;
        const float* Bk = Bbase + kt * 32;
        cp_async16(sa + (uint32_t)(arow * GA_LDA + apos * 4) * 4,
                   Ak + (size_t)arow * NN + apos * 4);
        #pragma unroll
        for (int c = 0; c < 6; c++) {
            int row = arow + c * 64;
            cp_async16(sb + (uint32_t)(row * GA_LDB + apos * 4) * 4,
                       Bk + (size_t)row * NN + apos * 4);
        }
        cp_commit();
    };

    cpAB(0, 0);

    for (int kt = 0; kt < GA_KT; kt++) {
        CP_WAIT(0);
        __syncthreads();
        if (kt + 1 < GA_KT) cpAB(kt + 1, (kt + 1) & 1);

        const float* As = smf + (kt & 1) * GA_STG;
        const float* Bf = As + GA_ASTG;

        #pragma unroll
        for (int g = 0; g < 4; g++) {
            const int kk = g * 8;
            uint32_t a[4], b[12][2];
            {
                int base = (wm + r) * GA_LDA + kk + c4;
                a[0] = f2tf32(As[base]);
                a[1] = f2tf32(As[base + 8 * GA_LDA]);
                a[2] = f2tf32(As[base + 4]);
                a[3] = f2tf32(As[base + 8 * GA_LDA + 4]);
            }
            #pragma unroll
            for (int ni = 0; ni < 12; ni++) {
                float2 v = *(const float2*)(Bf + (wn + ni * 8 + r) * GA_LDB + kk + 2 * c4);
                b[ni][0] = __float_as_uint(v.x);
                b[ni][1] = __float_as_uint(v.y);
            }
            #pragma unroll
            for (int ni = 0; ni < 12; ni++)
                mma_tf32(acc[ni], a, b[ni]);
        }
    }

    #pragma unroll
    for (int h = 0; h < 2; h++) {
        int row = m0 + wm + r + h * 8;
        float* dst = Ydst + (size_t)row * NPAD + wn;
        #pragma unroll
        for (int ni = 0; ni < 12; ni++) {
            int col = ni * 8 + c4 * 2;
            float2 v;
            v.x = acc[ni][h * 2 + 0];
            v.y = acc[ni][h * 2 + 1];
            *(float2*)(dst + col) = v;
        }
    }
}

// ---------------------------------------------------------------------------
// Reduce: Y = sum_{ks} Ypart[ks]  (deterministic fixed-order fp32 adds)
// ---------------------------------------------------------------------------
__global__ __launch_bounds__(256)
void reduce_ypart(const float4* __restrict__ yp, float4* __restrict__ y)
{
    constexpr size_t STRIDE = (size_t)NN * NPAD / 4;   // float4 elems per slice
    size_t i = (size_t)blockIdx.x * 256 + threadIdx.x;
    float4 s = yp[i];
    #pragma unroll
    for (int p = 1; p < KSPLIT; p++) {
        float4 v = yp[i + (size_t)p * STRIDE];
        s.x += v.x; s.y += v.y; s.z += v.z; s.w += v.w;
    }
    y[i] = s;
}

// ---------------------------------------------------------------------------
// GEMM_B: h1 = relu(Y @ W1 + b1)  [M=8192, N=1024(HPAD), K=384] — R11 proven
// ---------------------------------------------------------------------------
constexpr int GB_LDA = 36;
constexpr int GB_LDB = 40;
constexpr int GB_ASTG = 128 * GB_LDA;           // 4608 floats
constexpr int GB_BSTG = 256 * GB_LDB;           // 10240 floats
constexpr int GB_STG  = GB_ASTG + GB_BSTG;      // 14848
constexpr int GB_SMEM = 3 * GB_STG * 4;         // 178176 B
constexpr int GB_KT   = NPAD / 32;              // 12

__global__ __launch_bounds__(512, 1)
void gemmB(const float* __restrict__ Yb,
           const float* __restrict__ W1T,
           const float* __restrict__ bias,
           float* __restrict__ C)
{
    extern __shared__ float smf[];
    const uint32_t smb = (uint32_t)__cvta_generic_to_shared(smf);
    const int tid  = threadIdx.x;
    const int lane = tid & 31;
    const int wid  = tid >> 5;
    const int wm   = (wid & 3) * 32;
    const int wn   = (wid >> 2) * 64;
    const int r    = lane >> 2;
    const int c4   = lane & 3;
    const int m0   = blockIdx.y * 128;
    const int n0   = blockIdx.x * 256;

    const float* Abase = Yb  + (size_t)m0 * NPAD;
    const float* Bbase = W1T + (size_t)n0 * NPAD;

    float acc[2][8][4];
    #pragma unroll
    for (int i = 0; i < 2; i++)
        #pragma unroll
        for (int j = 0; j < 8; j++)
            #pragma unroll
            for (int q = 0; q < 4; q++) acc[i][j][q] = 0.f;

    const int row8 = tid >> 3, pos = tid & 7;

    auto cpAB = [&](int kt, int s) {
        const uint32_t sa = smb + (uint32_t)(s * GB_STG) * 4;
        const uint32_t sb = sa + (uint32_t)GB_ASTG * 4;
        const float* Ak = Abase + kt * 32;
        const float* Bk = Bbase + kt * 32;
        #pragma unroll
        for (int c = 0; c < 2; c++) {
            int row = row8 + c * 64;
            cp_async16(sa + (uint32_t)(row * GB_LDA + pos * 4) * 4,
                       Ak + (size_t)row * NPAD + pos * 4);
        }
        #pragma unroll
        for (int c = 0; c < 4; c++) {
            int row = row8 + c * 64;
            cp_async16(sb + (uint32_t)(row * GB_LDB + pos * 4) * 4,
                       Bk + (size_t)row * NPAD + pos * 4);
        }
        cp_commit();
    };

    cpAB(0, 0);
    cpAB(1, 1);

    for (int kt = 0; kt < GB_KT; kt++) {
        if (kt + 1 < GB_KT) { CP_WAIT(1); } else { CP_WAIT(0); }
        __syncthreads();
        if (kt + 2 < GB_KT) cpAB(kt + 2, (kt + 2) % 3);

        const float* As = smf + (kt % 3) * GB_STG;
        const float* Bf = As + GB_ASTG;

        #pragma unroll
        for (int g = 0; g < 4; g++) {
            const int kk = g * 8;
            uint32_t a[2][4], b[8][2];
            #pragma unroll
            for (int mi = 0; mi < 2; mi++) {
                int base = (wm + mi * 16 + r) * GB_LDA + kk + c4;
                a[mi][0] = f2tf32(As[base]);
                a[mi][1] = f2tf32(As[base + 8 * GB_LDA]);
                a[mi][2] = f2tf32(As[base + 4]);
                a[mi][3] = f2tf32(As[base + 8 * GB_LDA + 4]);
            }
            #pragma unroll
            for (int ni = 0; ni < 8; ni++) {
                float2 v = *(const float2*)(Bf + (wn + ni * 8 + r) * GB_LDB + kk + 2 * c4);
                b[ni][0] = __float_as_uint(v.x);
                b[ni][1] = __float_as_uint(v.y);
            }
            #pragma unroll
            for (int mi = 0; mi < 2; mi++)
                #pragma unroll
                for (int ni = 0; ni < 8; ni++)
                    mma_tf32(acc[mi][ni], a[mi], b[ni]);
        }
    }

    #pragma unroll
    for (int mi = 0; mi < 2; mi++) {
        #pragma unroll
        for (int h = 0; h < 2; h++) {
            int row = m0 + wm + mi * 16 + r + h * 8;
            float* dst = C + (size_t)row * HPAD + n0 + wn;
            #pragma unroll
            for (int ni = 0; ni < 8; ni++) {
                int col = ni * 8 + c4 * 2;
                float2 v;
                v.x = fmaxf(acc[mi][ni][h * 2 + 0] + bias[n0 + wn + col],     0.f);
                v.y = fmaxf(acc[mi][ni][h * 2 + 1] + bias[n0 + wn + col + 1], 0.f);
                *(float2*)(dst + col) = v;
            }
        }
    }
}

// ---------------------------------------------------------------------------
// transpose feat [8192, 343] -> featT [384, 8192], RNA, k-permuted, padded.
// ---------------------------------------------------------------------------
__global__ void transpose_feat(const float* __restrict__ in,
                               float* __restrict__ out)
{
    __shared__ float t[32][33];
    int x  = blockIdx.x * 32 + threadIdx.x;   // n (0..383)
    int y0 = blockIdx.y * 32;                 // k base
    #pragma unroll
    for (int j = threadIdx.y; j < 32; j += 8)
        t[j][threadIdx.x] = (x < IND) ? in[(size_t)(y0 + j) * IND + x] : 0.f;
    __syncthreads();
    int k  = y0 + threadIdx.x;
    int o  = k & 7;
    int kp = (k & ~7) | ((o < 4) ? (2 * o) : (2 * (o - 4) + 1));
    int n0 = blockIdx.x * 32;
    #pragma unroll
    for (int j = threadIdx.y; j < 32; j += 8)
        out[(size_t)(n0 + j) * NN + kp] = rna_f(t[threadIdx.x][j]);
}

// ---------------------------------------------------------------------------
// transpose W1 [343, 1000] -> W1T [1024, 384], RNA, k-permuted, padded.
// ---------------------------------------------------------------------------
__global__ void transpose_w1(const float* __restrict__ in,
                             float* __restrict__ out)
{
    __shared__ float t[32][33];
    int x  = blockIdx.x * 32 + threadIdx.x;   // n (0..1023)
    int y0 = blockIdx.y * 32;                 // k base (0..383)
    #pragma unroll
    for (int j = threadIdx.y; j < 32; j += 8) {
        int k = y0 + j;
        t[j][threadIdx.x] = (x < HIDD && k < IND) ? in[(size_t)k * HIDD + x] : 0.f;
    }
    __syncthreads();
    int k  = y0 + threadIdx.x;
    int o  = k & 7;
    int kp = (k & ~7) | ((o < 4) ? (2 * o) : (2 * (o - 4) + 1));
    int n0 = blockIdx.x * 32;
    #pragma unroll
    for (int j = threadIdx.y; j < 32; j += 8)
        out[(size_t)(n0 + j) * NPAD + kp] = rna_f(t[threadIdx.x][j]);
}

__global__ void pad_bias_kernel(const float* __restrict__ b1, float* __restrict__ b1p) {
    int i = threadIdx.x;
    b1p[i] = (i < HIDD) ? b1[i] : 0.f;
}

// ---------------------------------------------------------------------------
// LayerNorm(1000) + head, one warp per row, float4 loads.
// ---------------------------------------------------------------------------
__global__ __launch_bounds__(256)
void ln_head_kernel(const float* __restrict__ h,
                    const float* __restrict__ gamma,
                    const float* __restrict__ beta,
                    const float* __restrict__ Wm,
                    const float* __restrict__ bm,
                    float* __restrict__ out)
{
    const int row  = blockIdx.x * 8 + threadIdx.y;
    const int lane = threadIdx.x;
    const float4* hr = (const float4*)(h + (size_t)row * HPAD);
    const float4* g4 = (const float4*)gamma;
    const float4* be4 = (const float4*)beta;
    const float4* wm4 = (const float4*)Wm;

    float4 v[8];
    float s = 0.f, ss = 0.f;
    #pragma unroll
    for (int i = 0; i < 8; i++) {
        int idx = lane + 32 * i;
        float4 x = (idx < 250) ? hr[idx] : make_float4(0.f, 0.f, 0.f, 0.f);
        v[i] = x;
        s  += x.x + x.y + x.z + x.w;
        ss += x.x * x.x + x.y * x.y + x.z * x.z + x.w * x.w;
    }
    #pragma unroll
    for (int off = 16; off > 0; off >>= 1) {
        s  += __shfl_xor_sync(0xFFFFFFFF, s,  off);
        ss += __shfl_xor_sync(0xFFFFFFFF, ss, off);
    }
    const float mu   = s * (1.0f / HIDD);
    const float var  = ss * (1.0f / HIDD) - mu * mu;
    const float rinv = rsqrtf(var + EPS);

    float4 acc = make_float4(0.f, 0.f, 0.f, 0.f);
    #pragma unroll
    for (int i = 0; i < 8; i++) {
        int idx = lane + 32 * i;
        if (idx < 250) {
            float4 g = g4[idx], be = be4[idx];
            float xn0 = (v[i].x - mu) * rinv * g.x + be.x;
            float xn1 = (v[i].y - mu) * rinv * g.y + be.y;
            float xn2 = (v[i].z - mu) * rinv * g.z + be.z;
            float xn3 = (v[i].w - mu) * rinv * g.w + be.w;
            float4 w0 = wm4[idx * 4 + 0];
            float4 w1 = wm4[idx * 4 + 1];
            float4 w2 = wm4[idx * 4 + 2];
            float4 w3 = wm4[idx * 4 + 3];
            acc.x = fmaf(xn0, w0.x, fmaf(xn1, w1.x, fmaf(xn2, w2.x, fmaf(xn3, w3.x, acc.x))));
            acc.y = fmaf(xn0, w0.y, fmaf(xn1, w1.y, fmaf(xn2, w2.y, fmaf(xn3, w3.y, acc.y))));
            acc.z = fmaf(xn0, w0.z, fmaf(xn1, w1.z, fmaf(xn2, w2.z, fmaf(xn3, w3.z, acc.z))));
            acc.w = fmaf(xn0, w0.w, fmaf(xn1, w1.w, fmaf(xn2, w2.w, fmaf(xn3, w3.w, acc.w))));
        }
    }
    #pragma unroll
    for (int off = 16; off > 0; off >>= 1) {
        acc.x += __shfl_xor_sync(0xFFFFFFFF, acc.x, off);
        acc.y += __shfl_xor_sync(0xFFFFFFFF, acc.y, off);
        acc.z += __shfl_xor_sync(0xFFFFFFFF, acc.z, off);
        acc.w += __shfl_xor_sync(0xFFFFFFFF, acc.w, off);
    }
    if (lane == 0) {
        float4 b = *(const float4*)bm;
        float4 o;
        o.x = acc.x + b.x; o.y = acc.y + b.y;
        o.z = acc.z + b.z; o.w = acc.w + b.w;
        *(float4*)(out + (size_t)row * OUTD) = o;
    }
}

// ---------------------------------------------------------------------------
extern "C" void kernel_launch(void* const* d_in, const int* in_sizes, int n_in,
                              void* d_out, int out_size)
{
    const float* adj   = (const float*)d_in[0];
    const float* feat  = (const float*)d_in[1];
    const float* W1    = (const float*)d_in[2];
    const float* b1    = (const float*)d_in[3];
    const float* gamma = (const float*)d_in[4];
    const float* beta  = (const float*)d_in[5];
    const float* Wm    = (const float*)d_in[6];
    const float* bm    = (const float*)d_in[7];
    float* out = (float*)d_out;

    float *featT, *Ypart, *Yb, *W1T, *h1, *b1p;
    cudaGetSymbolAddress((void**)&featT, g_featT);
    cudaGetSymbolAddress((void**)&Ypart, g_Ypart);
    cudaGetSymbolAddress((void**)&Yb,    g_Y);
    cudaGetSymbolAddress((void**)&W1T,   g_W1T);
    cudaGetSymbolAddress((void**)&h1,    g_h1);
    cudaGetSymbolAddress((void**)&b1p,   g_b1p);

    cudaFuncSetAttribute(gemmA_split, cudaFuncAttributeMaxDynamicSharedMemorySize, GA_SMEM);
    cudaFuncSetAttribute(gemmB,       cudaFuncAttributeMaxDynamicSharedMemorySize, GB_SMEM);

    // prep: featT, W1T, padded bias
    {
        dim3 block(32, 8);
        dim3 gridF(NPAD / 32, NN / 32);
        transpose_feat<<<gridF, block>>>(feat, featT);
        dim3 gridW(HPAD / 32, NPAD / 32);
        transpose_w1<<<gridW, block>>>(W1, W1T);
        pad_bias_kernel<<<1, HPAD>>>(b1, b1p);
    }

    // GEMM_A split-K8: 1024 CTAs (7 unit-waves on 148 SMs)
    {
        dim3 grid(NN / 64, KSPLIT);
        gemmA_split<<<grid, 512, GA_SMEM>>>(adj, featT, Ypart);
    }

    // deterministic reduction: Y = sum(Ypart)
    reduce_ypart<<<(NN * NPAD / 4) / 256, 256>>>((const float4*)Ypart, (float4*)Yb);

    // GEMM_B: h1 = relu(Y @ W1 + b1)
    {
        dim3 grid(HPAD / 256, NN / 128);
        gemmB<<<grid, 512, GB_SMEM>>>(Yb, W1T, b1p, h1);
    }

    // LayerNorm + head
    {
        dim3 block(32, 8);
        ln_head_kernel<<<NN / 8, block>>>(h1, gamma, beta, Wm, bm, out);
    }
}

// round 14
// speedup vs baseline: 1.0816x; 1.0213x over previous
#include <cuda_runtime.h>
#include <math.h>
#include <stdint.h>

#define EPS 1e-5f
constexpr int NN   = 8192;
constexpr int IND  = 343;
constexpr int NPAD = 384;    // padded IND
constexpr int HIDD = 1000;
constexpr int HPAD = 1024;
constexpr int OUTD = 4;
constexpr int KSPLIT = 8;    // gemmA split-K factor
constexpr int NSM    = 148;  // persistent grid

// Scratch (allocation-free rule)
__device__ float g_featT[(size_t)NPAD * NN];            // feat^T, RNA, k-permuted, padded
__device__ float g_Ypart[(size_t)KSPLIT * NN * NPAD];   // split-K partials (100 MB)
__device__ float g_Y[(size_t)NN * NPAD];                // adj @ feat
__device__ float g_W1T[(size_t)HPAD * NPAD];            // W1^T, RNA, k-permuted, padded
__device__ float g_h1[(size_t)NN * HPAD];               // relu(Y @ W1 + b1)
__device__ float g_b1p[HPAD];

// ---------------------------------------------------------------------------
// helpers (base PTX only — sm_100 target has no tcgen05)
// ---------------------------------------------------------------------------
__device__ __forceinline__ uint32_t f2tf32(float v) {
    uint32_t r; asm("cvt.rna.tf32.f32 %0, %1;" : "=r"(r) : "f"(v)); return r;
}
__device__ __forceinline__ float rna_f(float v) { return __uint_as_float(f2tf32(v)); }

__device__ __forceinline__ void cp_async16(uint32_t dst, const void* src) {
    asm volatile("cp.async.cg.shared.global [%0], [%1], 16;\n" :: "r"(dst), "l"(src));
}
__device__ __forceinline__ void cp_commit() {
    asm volatile("cp.async.commit_group;\n" ::: "memory");
}
#define CP_WAIT(n) asm volatile("cp.async.wait_group %0;\n" :: "n"(n) : "memory")

__device__ __forceinline__ void mma_tf32(float* d, const uint32_t* a, const uint32_t* b) {
    asm volatile(
        "mma.sync.aligned.m16n8k8.row.col.f32.tf32.tf32.f32 "
        "{%0,%1,%2,%3}, {%4,%5,%6,%7}, {%8,%9}, {%0,%1,%2,%3};"
        : "+f"(d[0]), "+f"(d[1]), "+f"(d[2]), "+f"(d[3])
        : "r"(a[0]), "r"(a[1]), "r"(a[2]), "r"(a[3]), "r"(b[0]), "r"(b[1]));
}

// ---------------------------------------------------------------------------
// GEMM_A (persistent, split-K8): Ypart[ks][m-tile] for 1024 units.
// Grid = 148 CTAs; CTA b handles units b, b+148, ... (deterministic slots).
// Per unit: proven 64m x 384n tile, 512 thr (16 warps, 4m x 4n, warp 16x96),
// 2-stage cp.async pipeline that ROLLS ACROSS UNIT BOUNDARIES:
// at a unit's last ktile, the next unit's ktile 0 is prefetched, so the
// epilogue stores overlap the next prologue load.
// ---------------------------------------------------------------------------
constexpr int GA_LDA = 36;
constexpr int GA_LDB = 40;
constexpr int GA_ASTG = 64 * GA_LDA;            // 2304 floats
constexpr int GA_BSTG = NPAD * GA_LDB;          // 15360 floats
constexpr int GA_STG  = GA_ASTG + GA_BSTG;      // 17664 floats
constexpr int GA_SMEM = 2 * GA_STG * 4;         // 141312 B
constexpr int GA_KSLC = NN / KSPLIT;            // 1024 K per slice
constexpr int GA_KT   = GA_KSLC / 32;           // 32 ktiles per unit
constexpr int NUNITS  = (NN / 64) * KSPLIT;     // 1024

__global__ __launch_bounds__(512, 1)
void gemmA_persist(const float* __restrict__ adj,
                   const float* __restrict__ featT,
                   float* __restrict__ Ypart)
{
    extern __shared__ float smf[];
    const uint32_t smb = (uint32_t)__cvta_generic_to_shared(smf);
    const int tid  = threadIdx.x;
    const int lane = tid & 31;
    const int wid  = tid >> 5;
    const int wm   = (wid & 3) * 16;
    const int wn   = (wid >> 2) * 96;
    const int r    = lane >> 2;
    const int c4   = lane & 3;

    const int arow = tid >> 3;                  // 0..63
    const int apos = tid & 7;                   // 0..7

    auto cpAB = [&](const float* Ab, const float* Bb, int kt, int s) {
        const uint32_t sa = smb + (uint32_t)(s * GA_STG) * 4;
        const uint32_t sb = sa + (uint32_t)GA_ASTG * 4;
        const float* Ak = Ab + kt * 32;
        const float* Bk = Bb + kt * 32;
        cp_async16(sa + (uint32_t)(arow * GA_LDA + apos * 4) * 4,
                   Ak + (size_t)arow * NN + apos * 4);
        #pragma unroll
        for (int c = 0; c < 6; c++) {
            int row = arow + c * 64;
            cp_async16(sb + (uint32_t)(row * GA_LDB + apos * 4) * 4,
                       Bk + (size_t)row * NN + apos * 4);
        }
        cp_commit();
    };
    auto unit_bases = [&](int u, const float*& Ab, const float*& Bb) {
        int m0 = (u & 127) * 64;
        int ks = u >> 7;
        Ab = adj + (size_t)m0 * NN + (size_t)ks * GA_KSLC;
        Bb = featT + (size_t)ks * GA_KSLC;
    };

    int u = blockIdx.x;                          // < 148 < NUNITS always
    const float *Ab, *Bb, *Abn, *Bbn;
    unit_bases(u, Ab, Bb);
    cpAB(Ab, Bb, 0, 0);
    int stage = 0;

    for (; u < NUNITS; u += NSM) {
        float acc[12][4];
        #pragma unroll
        for (int j = 0; j < 12; j++)
            #pragma unroll
            for (int q = 0; q < 4; q++) acc[j][q] = 0.f;

        const bool has_next = (u + NSM < NUNITS);
        if (has_next) unit_bases(u + NSM, Abn, Bbn);

        for (int kt = 0; kt < GA_KT; kt++) {
            CP_WAIT(0);
            __syncthreads();
            if (kt + 1 < GA_KT)      cpAB(Ab,  Bb,  kt + 1, stage ^ 1);
            else if (has_next)       cpAB(Abn, Bbn, 0,      stage ^ 1);

            const float* As = smf + stage * GA_STG;
            const float* Bf = As + GA_ASTG;

            #pragma unroll
            for (int g = 0; g < 4; g++) {
                const int kk = g * 8;
                uint32_t a[4], b[12][2];
                {
                    int base = (wm + r) * GA_LDA + kk + c4;
                    a[0] = f2tf32(As[base]);
                    a[1] = f2tf32(As[base + 8 * GA_LDA]);
                    a[2] = f2tf32(As[base + 4]);
                    a[3] = f2tf32(As[base + 8 * GA_LDA + 4]);
                }
                #pragma unroll
                for (int ni = 0; ni < 12; ni++) {
                    float2 v = *(const float2*)(Bf + (wn + ni * 8 + r) * GA_LDB + kk + 2 * c4);
                    b[ni][0] = __float_as_uint(v.x);
                    b[ni][1] = __float_as_uint(v.y);
                }
                #pragma unroll
                for (int ni = 0; ni < 12; ni++)
                    mma_tf32(acc[ni], a, b[ni]);
            }
            stage ^= 1;
        }

        // epilogue for unit u (overlaps the next unit's in-flight prologue load)
        {
            int m0 = (u & 127) * 64;
            int ks = u >> 7;
            float* Ydst = Ypart + (size_t)ks * NN * NPAD;
            #pragma unroll
            for (int h = 0; h < 2; h++) {
                int row = m0 + wm + r + h * 8;
                float* dst = Ydst + (size_t)row * NPAD + wn;
                #pragma unroll
                for (int ni = 0; ni < 12; ni++) {
                    int col = ni * 8 + c4 * 2;
                    float2 v;
                    v.x = acc[ni][h * 2 + 0];
                    v.y = acc[ni][h * 2 + 1];
                    *(float2*)(dst + col) = v;
                }
            }
        }
        Ab = Abn; Bb = Bbn;
    }
}

// ---------------------------------------------------------------------------
// Reduce: Y = sum_{ks} Ypart[ks]  (deterministic fixed-order fp32 adds)
// ---------------------------------------------------------------------------
__global__ __launch_bounds__(256)
void reduce_ypart(const float4* __restrict__ yp, float4* __restrict__ y)
{
    constexpr size_t STRIDE = (size_t)NN * NPAD / 4;
    size_t i = (size_t)blockIdx.x * 256 + threadIdx.x;
    float4 s = yp[i];
    #pragma unroll
    for (int p = 1; p < KSPLIT; p++) {
        float4 v = yp[i + (size_t)p * STRIDE];
        s.x += v.x; s.y += v.y; s.z += v.z; s.w += v.w;
    }
    y[i] = s;
}

// ---------------------------------------------------------------------------
// GEMM_B: h1 = relu(Y @ W1 + b1)  [M=8192, N=1024(HPAD), K=352]
// (K trimmed: Y cols / W1T rows 343..351 are zero, 352..383 never read.)
// CTA 128m x 256n, 512 thr = 16 warps (4m x 4n), warp 32x64 (mi=2, ni=8).
// ---------------------------------------------------------------------------
constexpr int GB_LDA = 36;
constexpr int GB_LDB = 40;
constexpr int GB_ASTG = 128 * GB_LDA;           // 4608 floats
constexpr int GB_BSTG = 256 * GB_LDB;           // 10240 floats
constexpr int GB_STG  = GB_ASTG + GB_BSTG;      // 14848
constexpr int GB_SMEM = 3 * GB_STG * 4;         // 178176 B
constexpr int GB_KT   = 352 / 32;               // 11 ktiles

__global__ __launch_bounds__(512, 1)
void gemmB(const float* __restrict__ Yb,
           const float* __restrict__ W1T,
           const float* __restrict__ bias,
           float* __restrict__ C)
{
    extern __shared__ float smf[];
    const uint32_t smb = (uint32_t)__cvta_generic_to_shared(smf);
    const int tid  = threadIdx.x;
    const int lane = tid & 31;
    const int wid  = tid >> 5;
    const int wm   = (wid & 3) * 32;
    const int wn   = (wid >> 2) * 64;
    const int r    = lane >> 2;
    const int c4   = lane & 3;
    const int m0   = blockIdx.y * 128;
    const int n0   = blockIdx.x * 256;

    const float* Abase = Yb  + (size_t)m0 * NPAD;
    const float* Bbase = W1T + (size_t)n0 * NPAD;

    float acc[2][8][4];
    #pragma unroll
    for (int i = 0; i < 2; i++)
        #pragma unroll
        for (int j = 0; j < 8; j++)
            #pragma unroll
            for (int q = 0; q < 4; q++) acc[i][j][q] = 0.f;

    const int row8 = tid >> 3, pos = tid & 7;

    auto cpAB = [&](int kt, int s) {
        const uint32_t sa = smb + (uint32_t)(s * GB_STG) * 4;
        const uint32_t sb = sa + (uint32_t)GB_ASTG * 4;
        const float* Ak = Abase + kt * 32;
        const float* Bk = Bbase + kt * 32;
        #pragma unroll
        for (int c = 0; c < 2; c++) {
            int row = row8 + c * 64;
            cp_async16(sa + (uint32_t)(row * GB_LDA + pos * 4) * 4,
                       Ak + (size_t)row * NPAD + pos * 4);
        }
        #pragma unroll
        for (int c = 0; c < 4; c++) {
            int row = row8 + c * 64;
            cp_async16(sb + (uint32_t)(row * GB_LDB + pos * 4) * 4,
                       Bk + (size_t)row * NPAD + pos * 4);
        }
        cp_commit();
    };

    cpAB(0, 0);
    cpAB(1, 1);

    for (int kt = 0; kt < GB_KT; kt++) {
        if (kt + 1 < GB_KT) { CP_WAIT(1); } else { CP_WAIT(0); }
        __syncthreads();
        if (kt + 2 < GB_KT) cpAB(kt + 2, (kt + 2) % 3);

        const float* As = smf + (kt % 3) * GB_STG;
        const float* Bf = As + GB_ASTG;

        #pragma unroll
        for (int g = 0; g < 4; g++) {
            const int kk = g * 8;
            uint32_t a[2][4], b[8][2];
            #pragma unroll
            for (int mi = 0; mi < 2; mi++) {
                int base = (wm + mi * 16 + r) * GB_LDA + kk + c4;
                a[mi][0] = f2tf32(As[base]);
                a[mi][1] = f2tf32(As[base + 8 * GB_LDA]);
                a[mi][2] = f2tf32(As[base + 4]);
                a[mi][3] = f2tf32(As[base + 8 * GB_LDA + 4]);
            }
            #pragma unroll
            for (int ni = 0; ni < 8; ni++) {
                float2 v = *(const float2*)(Bf + (wn + ni * 8 + r) * GB_LDB + kk + 2 * c4);
                b[ni][0] = __float_as_uint(v.x);
                b[ni][1] = __float_as_uint(v.y);
            }
            #pragma unroll
            for (int mi = 0; mi < 2; mi++)
                #pragma unroll
                for (int ni = 0; ni < 8; ni++)
                    mma_tf32(acc[mi][ni], a[mi], b[ni]);
        }
    }

    #pragma unroll
    for (int mi = 0; mi < 2; mi++) {
        #pragma unroll
        for (int h = 0; h < 2; h++) {
            int row = m0 + wm + mi * 16 + r + h * 8;
            float* dst = C + (size_t)row * HPAD + n0 + wn;
            #pragma unroll
            for (int ni = 0; ni < 8; ni++) {
                int col = ni * 8 + c4 * 2;
                float2 v;
                v.x = fmaxf(acc[mi][ni][h * 2 + 0] + bias[n0 + wn + col],     0.f);
                v.y = fmaxf(acc[mi][ni][h * 2 + 1] + bias[n0 + wn + col + 1], 0.f);
                *(float2*)(dst + col) = v;
            }
        }
    }
}

// ---------------------------------------------------------------------------
// transpose feat [8192, 343] -> featT [384, 8192], RNA, k-permuted, padded.
// ---------------------------------------------------------------------------
__global__ void transpose_feat(const float* __restrict__ in,
                               float* __restrict__ out)
{
    __shared__ float t[32][33];
    int x  = blockIdx.x * 32 + threadIdx.x;
    int y0 = blockIdx.y * 32;
    #pragma unroll
    for (int j = threadIdx.y; j < 32; j += 8)
        t[j][threadIdx.x] = (x < IND) ? in[(size_t)(y0 + j) * IND + x] : 0.f;
    __syncthreads();
    int k  = y0 + threadIdx.x;
    int o  = k & 7;
    int kp = (k & ~7) | ((o < 4) ? (2 * o) : (2 * (o - 4) + 1));
    int n0 = blockIdx.x * 32;
    #pragma unroll
    for (int j = threadIdx.y; j < 32; j += 8)
        out[(size_t)(n0 + j) * NN + kp] = rna_f(t[threadIdx.x][j]);
}

// ---------------------------------------------------------------------------
// transpose W1 [343, 1000] -> W1T [1024, 384], RNA, k-permuted, padded.
// ---------------------------------------------------------------------------
__global__ void transpose_w1(const float* __restrict__ in,
                             float* __restrict__ out)
{
    __shared__ float t[32][33];
    int x  = blockIdx.x * 32 + threadIdx.x;
    int y0 = blockIdx.y * 32;
    #pragma unroll
    for (int j = threadIdx.y; j < 32; j += 8) {
        int k = y0 + j;
        t[j][threadIdx.x] = (x < HIDD && k < IND) ? in[(size_t)k * HIDD + x] : 0.f;
    }
    __syncthreads();
    int k  = y0 + threadIdx.x;
    int o  = k & 7;
    int kp = (k & ~7) | ((o < 4) ? (2 * o) : (2 * (o - 4) + 1));
    int n0 = blockIdx.x * 32;
    #pragma unroll
    for (int j = threadIdx.y; j < 32; j += 8)
        out[(size_t)(n0 + j) * NPAD + kp] = rna_f(t[threadIdx.x][j]);
}

__global__ void pad_bias_kernel(const float* __restrict__ b1, float* __restrict__ b1p) {
    int i = threadIdx.x;
    b1p[i] = (i < HIDD) ? b1[i] : 0.f;
}

// ---------------------------------------------------------------------------
// LayerNorm(1000) + head, one warp per row, float4 loads.
// ---------------------------------------------------------------------------
__global__ __launch_bounds__(256)
void ln_head_kernel(const float* __restrict__ h,
                    const float* __restrict__ gamma,
                    const float* __restrict__ beta,
                    const float* __restrict__ Wm,
                    const float* __restrict__ bm,
                    float* __restrict__ out)
{
    const int row  = blockIdx.x * 8 + threadIdx.y;
    const int lane = threadIdx.x;
    const float4* hr = (const float4*)(h + (size_t)row * HPAD);
    const float4* g4 = (const float4*)gamma;
    const float4* be4 = (const float4*)beta;
    const float4* wm4 = (const float4*)Wm;

    float4 v[8];
    float s = 0.f, ss = 0.f;
    #pragma unroll
    for (int i = 0; i < 8; i++) {
        int idx = lane + 32 * i;
        float4 x = (idx < 250) ? hr[idx] : make_float4(0.f, 0.f, 0.f, 0.f);
        v[i] = x;
        s  += x.x + x.y + x.z + x.w;
        ss += x.x * x.x + x.y * x.y + x.z * x.z + x.w * x.w;
    }
    #pragma unroll
    for (int off = 16; off > 0; off >>= 1) {
        s  += __shfl_xor_sync(0xFFFFFFFF, s,  off);
        ss += __shfl_xor_sync(0xFFFFFFFF, ss, off);
    }
    const float mu   = s * (1.0f / HIDD);
    const float var  = ss * (1.0f / HIDD) - mu * mu;
    const float rinv = rsqrtf(var + EPS);

    float4 acc = make_float4(0.f, 0.f, 0.f, 0.f);
    #pragma unroll
    for (int i = 0; i < 8; i++) {
        int idx = lane + 32 * i;
        if (idx < 250) {
            float4 g = g4[idx], be = be4[idx];
            float xn0 = (v[i].x - mu) * rinv * g.x + be.x;
            float xn1 = (v[i].y - mu) * rinv * g.y + be.y;
            float xn2 = (v[i].z - mu) * rinv * g.z + be.z;
            float xn3 = (v[i].w - mu) * rinv * g.w + be.w;
            float4 w0 = wm4[idx * 4 + 0];
            float4 w1 = wm4[idx * 4 + 1];
            float4 w2 = wm4[idx * 4 + 2];
            float4 w3 = wm4[idx * 4 + 3];
            acc.x = fmaf(xn0, w0.x, fmaf(xn1, w1.x, fmaf(xn2, w2.x, fmaf(xn3, w3.x, acc.x))));
            acc.y = fmaf(xn0, w0.y, fmaf(xn1, w1.y, fmaf(xn2, w2.y, fmaf(xn3, w3.y, acc.y))));
            acc.z = fmaf(xn0, w0.z, fmaf(xn1, w1.z, fmaf(xn2, w2.z, fmaf(xn3, w3.z, acc.z))));
            acc.w = fmaf(xn0, w0.w, fmaf(xn1, w1.w, fmaf(xn2, w2.w, fmaf(xn3, w3.w, acc.w))));
        }
    }
    #pragma unroll
    for (int off = 16; off > 0; off >>= 1) {
        acc.x += __shfl_xor_sync(0xFFFFFFFF, acc.x, off);
        acc.y += __shfl_xor_sync(0xFFFFFFFF, acc.y, off);
        acc.z += __shfl_xor_sync(0xFFFFFFFF, acc.z, off);
        acc.w += __shfl_xor_sync(0xFFFFFFFF, acc.w, off);
    }
    if (lane == 0) {
        float4 b = *(const float4*)bm;
        float4 o;
        o.x = acc.x + b.x; o.y = acc.y + b.y;
        o.z = acc.z + b.z; o.w = acc.w + b.w;
        *(float4*)(out + (size_t)row * OUTD) = o;
    }
}

// ---------------------------------------------------------------------------
extern "C" void kernel_launch(void* const* d_in, const int* in_sizes, int n_in,
                              void* d_out, int out_size)
{
    const float* adj   = (const float*)d_in[0];
    const float* feat  = (const float*)d_in[1];
    const float* W1    = (const float*)d_in[2];
    const float* b1    = (const float*)d_in[3];
    const float* gamma = (const float*)d_in[4];
    const float* beta  = (const float*)d_in[5];
    const float* Wm    = (const float*)d_in[6];
    const float* bm    = (const float*)d_in[7];
    float* out = (float*)d_out;

    float *featT, *Ypart, *Yb, *W1T, *h1, *b1p;
    cudaGetSymbolAddress((void**)&featT, g_featT);
    cudaGetSymbolAddress((void**)&Ypart, g_Ypart);
    cudaGetSymbolAddress((void**)&Yb,    g_Y);
    cudaGetSymbolAddress((void**)&W1T,   g_W1T);
    cudaGetSymbolAddress((void**)&h1,    g_h1);
    cudaGetSymbolAddress((void**)&b1p,   g_b1p);

    cudaFuncSetAttribute(gemmA_persist, cudaFuncAttributeMaxDynamicSharedMemorySize, GA_SMEM);
    cudaFuncSetAttribute(gemmB,         cudaFuncAttributeMaxDynamicSharedMemorySize, GB_SMEM);

    // prep: featT, W1T, padded bias
    {
        dim3 block(32, 8);
        dim3 gridF(NPAD / 32, NN / 32);
        transpose_feat<<<gridF, block>>>(feat, featT);
        dim3 gridW(HPAD / 32, NPAD / 32);
        transpose_w1<<<gridW, block>>>(W1, W1T);
        pad_bias_kernel<<<1, HPAD>>>(b1, b1p);
    }

    // GEMM_A: persistent 148 CTAs over 1024 split-K units
    gemmA_persist<<<NSM, 512, GA_SMEM>>>(adj, featT, Ypart);

    // deterministic reduction: Y = sum(Ypart)
    reduce_ypart<<<(NN * NPAD / 4) / 256, 256>>>((const float4*)Ypart, (float4*)Yb);

    // GEMM_B: h1 = relu(Y @ W1 + b1)
    {
        dim3 grid(HPAD / 256, NN / 128);
        gemmB<<<grid, 512, GB_SMEM>>>(Yb, W1T, b1p, h1);
    }

    // LayerNorm + head
    {
        dim3 block(32, 8);
        ln_head_kernel<<<NN / 8, block>>>(h1, gamma, beta, Wm, bm, out);
    }
}

// round 15
// speedup vs baseline: 1.1387x; 1.0528x over previous
#include <cuda_runtime.h>
#include <math.h>
#include <stdint.h>

#define EPS 1e-5f
constexpr int NN   = 8192;
constexpr int IND  = 343;
constexpr int NPAD = 352;    // padded IND (4 warps x 88, ni=11)
constexpr int HIDD = 1000;
constexpr int HPAD = 1024;
constexpr int OUTD = 4;
constexpr int KSPLIT = 8;    // gemmA split-K factor
constexpr int NSM    = 148;  // persistent grid

// Scratch (allocation-free rule)
__device__ float g_featT[(size_t)NPAD * NN];            // feat^T, RNA, k-permuted, padded
__device__ float g_Ypart[(size_t)KSPLIT * NN * NPAD];   // split-K partials (92 MB)
__device__ float g_Y[(size_t)NN * NPAD];                // adj @ feat
__device__ float g_W1T[(size_t)HPAD * NPAD];            // W1^T, RNA, k-permuted, padded
__device__ float g_h1[(size_t)NN * HPAD];               // relu(Y @ W1 + b1)
__device__ float g_b1p[HPAD];

// ---------------------------------------------------------------------------
// helpers (base PTX only — sm_100 target has no tcgen05)
// ---------------------------------------------------------------------------
__device__ __forceinline__ uint32_t f2tf32(float v) {
    uint32_t r; asm("cvt.rna.tf32.f32 %0, %1;" : "=r"(r) : "f"(v)); return r;
}
__device__ __forceinline__ float rna_f(float v) { return __uint_as_float(f2tf32(v)); }

__device__ __forceinline__ void cp_async16(uint32_t dst, const void* src) {
    asm volatile("cp.async.cg.shared.global [%0], [%1], 16;\n" :: "r"(dst), "l"(src));
}
__device__ __forceinline__ void cp_commit() {
    asm volatile("cp.async.commit_group;\n" ::: "memory");
}
#define CP_WAIT(n) asm volatile("cp.async.wait_group %0;\n" :: "n"(n) : "memory")

__device__ __forceinline__ void mma_tf32(float* d, const uint32_t* a, const uint32_t* b) {
    asm volatile(
        "mma.sync.aligned.m16n8k8.row.col.f32.tf32.tf32.f32 "
        "{%0,%1,%2,%3}, {%4,%5,%6,%7}, {%8,%9}, {%0,%1,%2,%3};"
        : "+f"(d[0]), "+f"(d[1]), "+f"(d[2]), "+f"(d[3])
        : "r"(a[0]), "r"(a[1]), "r"(a[2]), "r"(a[3]), "r"(b[0]), "r"(b[1]));
}

// ---------------------------------------------------------------------------
// GEMM_A (persistent, split-K8): Ypart[ks][m-tile] for 1024 units.
// Grid = 148 CTAs; CTA b handles units b, b+148, ... (deterministic slots).
// Per unit: 64m x 352n tile, 512 thr (16 warps, 4m x 4n, warp 16x88, ni=11),
// 2-stage cp.async pipeline rolling across unit boundaries.
// ---------------------------------------------------------------------------
constexpr int GA_LDA = 36;
constexpr int GA_LDB = 40;
constexpr int GA_ASTG = 64 * GA_LDA;            // 2304 floats
constexpr int GA_BSTG = NPAD * GA_LDB;          // 14080 floats
constexpr int GA_STG  = GA_ASTG + GA_BSTG;      // 16384 floats = 64 KB
constexpr int GA_SMEM = 2 * GA_STG * 4;         // 131072 B
constexpr int GA_KSLC = NN / KSPLIT;            // 1024 K per slice
constexpr int GA_KT   = GA_KSLC / 32;           // 32 ktiles per unit
constexpr int NUNITS  = (NN / 64) * KSPLIT;     // 1024
constexpr int NI      = 11;                      // n-frags per warp (88 cols)

__global__ __launch_bounds__(512, 1)
void gemmA_persist(const float* __restrict__ adj,
                   const float* __restrict__ featT,
                   float* __restrict__ Ypart)
{
    extern __shared__ float smf[];
    const uint32_t smb = (uint32_t)__cvta_generic_to_shared(smf);
    const int tid  = threadIdx.x;
    const int lane = tid & 31;
    const int wid  = tid >> 5;
    const int wm   = (wid & 3) * 16;
    const int wn   = (wid >> 2) * 88;
    const int r    = lane >> 2;
    const int c4   = lane & 3;

    const int arow = tid >> 3;                  // 0..63
    const int apos = tid & 7;                   // 0..7

    auto cpAB = [&](const float* Ab, const float* Bb, int kt, int s) {
        const uint32_t sa = smb + (uint32_t)(s * GA_STG) * 4;
        const uint32_t sb = sa + (uint32_t)GA_ASTG * 4;
        const float* Ak = Ab + kt * 32;
        const float* Bk = Bb + kt * 32;
        cp_async16(sa + (uint32_t)(arow * GA_LDA + apos * 4) * 4,
                   Ak + (size_t)arow * NN + apos * 4);
        #pragma unroll
        for (int c = 0; c < 6; c++) {
            int row = arow + c * 64;            // 0..383; rows >= 352 skipped
            if (row < NPAD)
                cp_async16(sb + (uint32_t)(row * GA_LDB + apos * 4) * 4,
                           Bk + (size_t)row * NN + apos * 4);
        }
        cp_commit();
    };
    auto unit_bases = [&](int u, const float*& Ab, const float*& Bb) {
        int m0 = (u & 127) * 64;
        int ks = u >> 7;
        Ab = adj + (size_t)m0 * NN + (size_t)ks * GA_KSLC;
        Bb = featT + (size_t)ks * GA_KSLC;
    };

    int u = blockIdx.x;                          // < 148 < NUNITS always
    const float *Ab, *Bb, *Abn, *Bbn;
    unit_bases(u, Ab, Bb);
    cpAB(Ab, Bb, 0, 0);
    int stage = 0;

    for (; u < NUNITS; u += NSM) {
        float acc[NI][4];
        #pragma unroll
        for (int j = 0; j < NI; j++)
            #pragma unroll
            for (int q = 0; q < 4; q++) acc[j][q] = 0.f;

        const bool has_next = (u + NSM < NUNITS);
        if (has_next) unit_bases(u + NSM, Abn, Bbn);

        for (int kt = 0; kt < GA_KT; kt++) {
            CP_WAIT(0);
            __syncthreads();
            if (kt + 1 < GA_KT)      cpAB(Ab,  Bb,  kt + 1, stage ^ 1);
            else if (has_next)       cpAB(Abn, Bbn, 0,      stage ^ 1);

            const float* As = smf + stage * GA_STG;
            const float* Bf = As + GA_ASTG;

            #pragma unroll
            for (int g = 0; g < 4; g++) {
                const int kk = g * 8;
                uint32_t a[4], b[NI][2];
                {
                    int base = (wm + r) * GA_LDA + kk + c4;
                    a[0] = f2tf32(As[base]);
                    a[1] = f2tf32(As[base + 8 * GA_LDA]);
                    a[2] = f2tf32(As[base + 4]);
                    a[3] = f2tf32(As[base + 8 * GA_LDA + 4]);
                }
                #pragma unroll
                for (int ni = 0; ni < NI; ni++) {
                    float2 v = *(const float2*)(Bf + (wn + ni * 8 + r) * GA_LDB + kk + 2 * c4);
                    b[ni][0] = __float_as_uint(v.x);
                    b[ni][1] = __float_as_uint(v.y);
                }
                #pragma unroll
                for (int ni = 0; ni < NI; ni++)
                    mma_tf32(acc[ni], a, b[ni]);
            }
            stage ^= 1;
        }

        // epilogue for unit u (overlaps the next unit's in-flight prologue load)
        {
            int m0 = (u & 127) * 64;
            int ks = u >> 7;
            float* Ydst = Ypart + (size_t)ks * NN * NPAD;
            #pragma unroll
            for (int h = 0; h < 2; h++) {
                int row = m0 + wm + r + h * 8;
                float* dst = Ydst + (size_t)row * NPAD + wn;
                #pragma unroll
                for (int ni = 0; ni < NI; ni++) {
                    int col = ni * 8 + c4 * 2;
                    float2 v;
                    v.x = acc[ni][h * 2 + 0];
                    v.y = acc[ni][h * 2 + 1];
                    *(float2*)(dst + col) = v;
                }
            }
        }
        Ab = Abn; Bb = Bbn;
    }
}

// ---------------------------------------------------------------------------
// Reduce: Y = sum_{ks} Ypart[ks]  (deterministic fixed-order fp32 adds)
// NN*NPAD/4 = 720896 float4s = 2816 blocks x 256 threads.
// ---------------------------------------------------------------------------
__global__ __launch_bounds__(256)
void reduce_ypart(const float4* __restrict__ yp, float4* __restrict__ y)
{
    constexpr size_t STRIDE = (size_t)NN * NPAD / 4;
    size_t i = (size_t)blockIdx.x * 256 + threadIdx.x;
    float4 s = yp[i];
    #pragma unroll
    for (int p = 1; p < KSPLIT; p++) {
        float4 v = yp[i + (size_t)p * STRIDE];
        s.x += v.x; s.y += v.y; s.z += v.z; s.w += v.w;
    }
    y[i] = s;
}

// ---------------------------------------------------------------------------
// GEMM_B: h1 = relu(Y @ W1 + b1)  [M=8192, N=1024(HPAD), K=352]
// CTA 128m x 256n, 512 thr = 16 warps (4m x 4n), warp 32x64 (mi=2, ni=8).
// 3-stage cp.async, one barrier per ktile. lda = NPAD = 352 (16B-aligned rows).
// ---------------------------------------------------------------------------
constexpr int GB_LDA = 36;
constexpr int GB_LDB = 40;
constexpr int GB_ASTG = 128 * GB_LDA;           // 4608 floats
constexpr int GB_BSTG = 256 * GB_LDB;           // 10240 floats
constexpr int GB_STG  = GB_ASTG + GB_BSTG;      // 14848
constexpr int GB_SMEM = 3 * GB_STG * 4;         // 178176 B
constexpr int GB_KT   = NPAD / 32;              // 11 ktiles

__global__ __launch_bounds__(512, 1)
void gemmB(const float* __restrict__ Yb,
           const float* __restrict__ W1T,
           const float* __restrict__ bias,
           float* __restrict__ C)
{
    extern __shared__ float smf[];
    const uint32_t smb = (uint32_t)__cvta_generic_to_shared(smf);
    const int tid  = threadIdx.x;
    const int lane = tid & 31;
    const int wid  = tid >> 5;
    const int wm   = (wid & 3) * 32;
    const int wn   = (wid >> 2) * 64;
    const int r    = lane >> 2;
    const int c4   = lane & 3;
    const int m0   = blockIdx.y * 128;
    const int n0   = blockIdx.x * 256;

    const float* Abase = Yb  + (size_t)m0 * NPAD;
    const float* Bbase = W1T + (size_t)n0 * NPAD;

    float acc[2][8][4];
    #pragma unroll
    for (int i = 0; i < 2; i++)
        #pragma unroll
        for (int j = 0; j < 8; j++)
            #pragma unroll
            for (int q = 0; q < 4; q++) acc[i][j][q] = 0.f;

    const int row8 = tid >> 3, pos = tid & 7;

    auto cpAB = [&](int kt, int s) {
        const uint32_t sa = smb + (uint32_t)(s * GB_STG) * 4;
        const uint32_t sb = sa + (uint32_t)GB_ASTG * 4;
        const float* Ak = Abase + kt * 32;
        const float* Bk = Bbase + kt * 32;
        #pragma unroll
        for (int c = 0; c < 2; c++) {
            int row = row8 + c * 64;
            cp_async16(sa + (uint32_t)(row * GB_LDA + pos * 4) * 4,
                       Ak + (size_t)row * NPAD + pos * 4);
        }
        #pragma unroll
        for (int c = 0; c < 4; c++) {
            int row = row8 + c * 64;
            cp_async16(sb + (uint32_t)(row * GB_LDB + pos * 4) * 4,
                       Bk + (size_t)row * NPAD + pos * 4);
        }
        cp_commit();
    };

    cpAB(0, 0);
    cpAB(1, 1);

    for (int kt = 0; kt < GB_KT; kt++) {
        if (kt + 1 < GB_KT) { CP_WAIT(1); } else { CP_WAIT(0); }
        __syncthreads();
        if (kt + 2 < GB_KT) cpAB(kt + 2, (kt + 2) % 3);

        const float* As = smf + (kt % 3) * GB_STG;
        const float* Bf = As + GB_ASTG;

        #pragma unroll
        for (int g = 0; g < 4; g++) {
            const int kk = g * 8;
            uint32_t a[2][4], b[8][2];
            #pragma unroll
            for (int mi = 0; mi < 2; mi++) {
                int base = (wm + mi * 16 + r) * GB_LDA + kk + c4;
                a[mi][0] = f2tf32(As[base]);
                a[mi][1] = f2tf32(As[base + 8 * GB_LDA]);
                a[mi][2] = f2tf32(As[base + 4]);
                a[mi][3] = f2tf32(As[base + 8 * GB_LDA + 4]);
            }
            #pragma unroll
            for (int ni = 0; ni < 8; ni++) {
                float2 v = *(const float2*)(Bf + (wn + ni * 8 + r) * GB_LDB + kk + 2 * c4);
                b[ni][0] = __float_as_uint(v.x);
                b[ni][1] = __float_as_uint(v.y);
            }
            #pragma unroll
            for (int mi = 0; mi < 2; mi++)
                #pragma unroll
                for (int ni = 0; ni < 8; ni++)
                    mma_tf32(acc[mi][ni], a[mi], b[ni]);
        }
    }

    #pragma unroll
    for (int mi = 0; mi < 2; mi++) {
        #pragma unroll
        for (int h = 0; h < 2; h++) {
            int row = m0 + wm + mi * 16 + r + h * 8;
            float* dst = C + (size_t)row * HPAD + n0 + wn;
            #pragma unroll
            for (int ni = 0; ni < 8; ni++) {
                int col = ni * 8 + c4 * 2;
                float2 v;
                v.x = fmaxf(acc[mi][ni][h * 2 + 0] + bias[n0 + wn + col],     0.f);
                v.y = fmaxf(acc[mi][ni][h * 2 + 1] + bias[n0 + wn + col + 1], 0.f);
                *(float2*)(dst + col) = v;
            }
        }
    }
}

// ---------------------------------------------------------------------------
// transpose feat [8192, 343] -> featT [352, 8192], RNA, k-permuted, padded.
// ---------------------------------------------------------------------------
__global__ void transpose_feat(const float* __restrict__ in,
                               float* __restrict__ out)
{
    __shared__ float t[32][33];
    int x  = blockIdx.x * 32 + threadIdx.x;   // n (0..351)
    int y0 = blockIdx.y * 32;
    #pragma unroll
    for (int j = threadIdx.y; j < 32; j += 8)
        t[j][threadIdx.x] = (x < IND) ? in[(size_t)(y0 + j) * IND + x] : 0.f;
    __syncthreads();
    int k  = y0 + threadIdx.x;
    int o  = k & 7;
    int kp = (k & ~7) | ((o < 4) ? (2 * o) : (2 * (o - 4) + 1));
    int n0 = blockIdx.x * 32;
    #pragma unroll
    for (int j = threadIdx.y; j < 32; j += 8)
        out[(size_t)(n0 + j) * NN + kp] = rna_f(t[threadIdx.x][j]);
}

// ---------------------------------------------------------------------------
// transpose W1 [343, 1000] -> W1T [1024, 352], RNA, k-permuted, padded.
// ---------------------------------------------------------------------------
__global__ void transpose_w1(const float* __restrict__ in,
                             float* __restrict__ out)
{
    __shared__ float t[32][33];
    int x  = blockIdx.x * 32 + threadIdx.x;   // n (0..1023)
    int y0 = blockIdx.y * 32;                 // k base (0..351)
    #pragma unroll
    for (int j = threadIdx.y; j < 32; j += 8) {
        int k = y0 + j;
        t[j][threadIdx.x] = (x < HIDD && k < IND) ? in[(size_t)k * HIDD + x] : 0.f;
    }
    __syncthreads();
    int k  = y0 + threadIdx.x;
    int o  = k & 7;
    int kp = (k & ~7) | ((o < 4) ? (2 * o) : (2 * (o - 4) + 1));
    int n0 = blockIdx.x * 32;
    #pragma unroll
    for (int j = threadIdx.y; j < 32; j += 8)
        out[(size_t)(n0 + j) * NPAD + kp] = rna_f(t[threadIdx.x][j]);
}

__global__ void pad_bias_kernel(const float* __restrict__ b1, float* __restrict__ b1p) {
    int i = threadIdx.x;
    b1p[i] = (i < HIDD) ? b1[i] : 0.f;
}

// ---------------------------------------------------------------------------
// LayerNorm(1000) + head, one warp per row, float4 loads.
// ---------------------------------------------------------------------------
__global__ __launch_bounds__(256)
void ln_head_kernel(const float* __restrict__ h,
                    const float* __restrict__ gamma,
                    const float* __restrict__ beta,
                    const float* __restrict__ Wm,
                    const float* __restrict__ bm,
                    float* __restrict__ out)
{
    const int row  = blockIdx.x * 8 + threadIdx.y;
    const int lane = threadIdx.x;
    const float4* hr = (const float4*)(h + (size_t)row * HPAD);
    const float4* g4 = (const float4*)gamma;
    const float4* be4 = (const float4*)beta;
    const float4* wm4 = (const float4*)Wm;

    float4 v[8];
    float s = 0.f, ss = 0.f;
    #pragma unroll
    for (int i = 0; i < 8; i++) {
        int idx = lane + 32 * i;
        float4 x = (idx < 250) ? hr[idx] : make_float4(0.f, 0.f, 0.f, 0.f);
        v[i] = x;
        s  += x.x + x.y + x.z + x.w;
        ss += x.x * x.x + x.y * x.y + x.z * x.z + x.w * x.w;
    }
    #pragma unroll
    for (int off = 16; off > 0; off >>= 1) {
        s  += __shfl_xor_sync(0xFFFFFFFF, s,  off);
        ss += __shfl_xor_sync(0xFFFFFFFF, ss, off);
    }
    const float mu   = s * (1.0f / HIDD);
    const float var  = ss * (1.0f / HIDD) - mu * mu;
    const float rinv = rsqrtf(var + EPS);

    float4 acc = make_float4(0.f, 0.f, 0.f, 0.f);
    #pragma unroll
    for (int i = 0; i < 8; i++) {
        int idx = lane + 32 * i;
        if (idx < 250) {
            float4 g = g4[idx], be = be4[idx];
            float xn0 = (v[i].x - mu) * rinv * g.x + be.x;
            float xn1 = (v[i].y - mu) * rinv * g.y + be.y;
            float xn2 = (v[i].z - mu) * rinv * g.z + be.z;
            float xn3 = (v[i].w - mu) * rinv * g.w + be.w;
            float4 w0 = wm4[idx * 4 + 0];
            float4 w1 = wm4[idx * 4 + 1];
            float4 w2 = wm4[idx * 4 + 2];
            float4 w3 = wm4[idx * 4 + 3];
            acc.x = fmaf(xn0, w0.x, fmaf(xn1, w1.x, fmaf(xn2, w2.x, fmaf(xn3, w3.x, acc.x))));
            acc.y = fmaf(xn0, w0.y, fmaf(xn1, w1.y, fmaf(xn2, w2.y, fmaf(xn3, w3.y, acc.y))));
            acc.z = fmaf(xn0, w0.z, fmaf(xn1, w1.z, fmaf(xn2, w2.z, fmaf(xn3, w3.z, acc.z))));
            acc.w = fmaf(xn0, w0.w, fmaf(xn1, w1.w, fmaf(xn2, w2.w, fmaf(xn3, w3.w, acc.w))));
        }
    }
    #pragma unroll
    for (int off = 16; off > 0; off >>= 1) {
        acc.x += __shfl_xor_sync(0xFFFFFFFF, acc.x, off);
        acc.y += __shfl_xor_sync(0xFFFFFFFF, acc.y, off);
        acc.z += __shfl_xor_sync(0xFFFFFFFF, acc.z, off);
        acc.w += __shfl_xor_sync(0xFFFFFFFF, acc.w, off);
    }
    if (lane == 0) {
        float4 b = *(const float4*)bm;
        float4 o;
        o.x = acc.x + b.x; o.y = acc.y + b.y;
        o.z = acc.z + b.z; o.w = acc.w + b.w;
        *(float4*)(out + (size_t)row * OUTD) = o;
    }
}

// ---------------------------------------------------------------------------
extern "C" void kernel_launch(void* const* d_in, const int* in_sizes, int n_in,
                              void* d_out, int out_size)
{
    const float* adj   = (const float*)d_in[0];
    const float* feat  = (const float*)d_in[1];
    const float* W1    = (const float*)d_in[2];
    const float* b1    = (const float*)d_in[3];
    const float* gamma = (const float*)d_in[4];
    const float* beta  = (const float*)d_in[5];
    const float* Wm    = (const float*)d_in[6];
    const float* bm    = (const float*)d_in[7];
    float* out = (float*)d_out;

    float *featT, *Ypart, *Yb, *W1T, *h1, *b1p;
    cudaGetSymbolAddress((void**)&featT, g_featT);
    cudaGetSymbolAddress((void**)&Ypart, g_Ypart);
    cudaGetSymbolAddress((void**)&Yb,    g_Y);
    cudaGetSymbolAddress((void**)&W1T,   g_W1T);
    cudaGetSymbolAddress((void**)&h1,    g_h1);
    cudaGetSymbolAddress((void**)&b1p,   g_b1p);

    cudaFuncSetAttribute(gemmA_persist, cudaFuncAttributeMaxDynamicSharedMemorySize, GA_SMEM);
    cudaFuncSetAttribute(gemmB,         cudaFuncAttributeMaxDynamicSharedMemorySize, GB_SMEM);

    // prep: featT, W1T, padded bias
    {
        dim3 block(32, 8);
        dim3 gridF(NPAD / 32, NN / 32);
        transpose_feat<<<gridF, block>>>(feat, featT);
        dim3 gridW(HPAD / 32, NPAD / 32);
        transpose_w1<<<gridW, block>>>(W1, W1T);
        pad_bias_kernel<<<1, HPAD>>>(b1, b1p);
    }

    // GEMM_A: persistent 148 CTAs over 1024 split-K units
    gemmA_persist<<<NSM, 512, GA_SMEM>>>(adj, featT, Ypart);

    // deterministic reduction: Y = sum(Ypart)
    reduce_ypart<<<(NN * NPAD / 4) / 256, 256>>>((const float4*)Ypart, (float4*)Yb);

    // GEMM_B: h1 = relu(Y @ W1 + b1)
    {
        dim3 grid(HPAD / 256, NN / 128);
        gemmB<<<grid, 512, GB_SMEM>>>(Yb, W1T, b1p, h1);
    }

    // LayerNorm + head
    {
        dim3 block(32, 8);
        ln_head_kernel<<<NN / 8, block>>>(h1, gamma, beta, Wm, bm, out);
    }
}

// round 16
// speedup vs baseline: 1.2451x; 1.0934x over previous
#include <cuda_runtime.h>
#include <math.h>
#include <stdint.h>

#define EPS 1e-5f
constexpr int NN   = 8192;
constexpr int IND  = 343;
constexpr int NPAD = 352;    // padded IND
constexpr int HIDD = 1000;
constexpr int HPAD = 1024;
constexpr int OUTD = 4;
constexpr int KSPLIT = 8;    // gemmA split-K factor
constexpr int NSM    = 148;  // persistent grid

// Scratch (allocation-free rule)
__device__ float g_featT[(size_t)NPAD * NN];            // feat^T, RNA, k-permuted, padded
__device__ float g_Ypart[(size_t)KSPLIT * NN * NPAD];   // split-K partials (92 MB)
__device__ float g_Y[(size_t)NN * NPAD];                // adj @ feat
__device__ float g_W1T[(size_t)HPAD * NPAD];            // W1^T, RNA, k-permuted, padded
__device__ float g_h1[(size_t)NN * HPAD];               // relu(Y @ W1 + b1)
__device__ float g_b1p[HPAD];

// ---------------------------------------------------------------------------
// helpers (base PTX only — sm_100 target has no tcgen05)
// ---------------------------------------------------------------------------
__device__ __forceinline__ uint32_t f2tf32(float v) {
    uint32_t r; asm("cvt.rna.tf32.f32 %0, %1;" : "=r"(r) : "f"(v)); return r;
}
__device__ __forceinline__ float rna_f(float v) { return __uint_as_float(f2tf32(v)); }

__device__ __forceinline__ void cp_async16(uint32_t dst, const void* src) {
    asm volatile("cp.async.cg.shared.global [%0], [%1], 16;\n" :: "r"(dst), "l"(src));
}
__device__ __forceinline__ void cp_commit() {
    asm volatile("cp.async.commit_group;\n" ::: "memory");
}
#define CP_WAIT(n) asm volatile("cp.async.wait_group %0;\n" :: "n"(n) : "memory")

__device__ __forceinline__ void mma_tf32(float* d, const uint32_t* a, const uint32_t* b) {
    asm volatile(
        "mma.sync.aligned.m16n8k8.row.col.f32.tf32.tf32.f32 "
        "{%0,%1,%2,%3}, {%4,%5,%6,%7}, {%8,%9}, {%0,%1,%2,%3};"
        : "+f"(d[0]), "+f"(d[1]), "+f"(d[2]), "+f"(d[3])
        : "r"(a[0]), "r"(a[1]), "r"(a[2]), "r"(a[3]), "r"(b[0]), "r"(b[1]));
}

// ---------------------------------------------------------------------------
// GEMM_A (persistent, split-K8): Ypart[ks][m-tile] for 1024 units.
// Grid = 148 CTAs; CTA b handles units b, b+148, ... (deterministic slots).
// Per unit: 64m x 352n tile, 256 thr = 8 warps (2m x 4n), warp 32x88
// (mi=2, ni=11 -> 22 MMAs per k-group per warp; R6-proven MMA density).
// 2-stage cp.async pipeline rolling across unit boundaries.
// ---------------------------------------------------------------------------
constexpr int GA_LDA = 36;
constexpr int GA_LDB = 40;
constexpr int GA_ASTG = 64 * GA_LDA;            // 2304 floats
constexpr int GA_BSTG = NPAD * GA_LDB;          // 14080 floats
constexpr int GA_STG  = GA_ASTG + GA_BSTG;      // 16384 floats = 64 KB
constexpr int GA_SMEM = 2 * GA_STG * 4;         // 131072 B
constexpr int GA_KSLC = NN / KSPLIT;            // 1024 K per slice
constexpr int GA_KT   = GA_KSLC / 32;           // 32 ktiles per unit
constexpr int NUNITS  = (NN / 64) * KSPLIT;     // 1024
constexpr int NI      = 11;                      // n-frags per warp (88 cols)

__global__ __launch_bounds__(256, 1)
void gemmA_persist(const float* __restrict__ adj,
                   const float* __restrict__ featT,
                   float* __restrict__ Ypart)
{
    extern __shared__ float smf[];
    const uint32_t smb = (uint32_t)__cvta_generic_to_shared(smf);
    const int tid  = threadIdx.x;
    const int lane = tid & 31;
    const int wid  = tid >> 5;                  // 0..7
    const int wm   = (wid & 1) * 32;            // 2 m-warps x 32 rows
    const int wn   = (wid >> 1) * 88;           // 4 n-warps x 88 cols
    const int r    = lane >> 2;
    const int c4   = lane & 3;

    auto cpAB = [&](const float* Ab, const float* Bb, int kt, int s) {
        const uint32_t sa = smb + (uint32_t)(s * GA_STG) * 4;
        const uint32_t sb = sa + (uint32_t)GA_ASTG * 4;
        const float* Ak = Ab + kt * 32;
        const float* Bk = Bb + kt * 32;
        // A: 512 16B-chunks, 2 per thread
        #pragma unroll
        for (int c = 0; c < 2; c++) {
            int chunk = tid + c * 256;
            int row = chunk >> 3, pos = chunk & 7;
            cp_async16(sa + (uint32_t)(row * GA_LDA + pos * 4) * 4,
                       Ak + (size_t)row * NN + pos * 4);
        }
        // B: 2816 chunks = 11 per thread exactly (352 rows x 8)
        #pragma unroll
        for (int c = 0; c < 11; c++) {
            int chunk = tid + c * 256;
            int row = chunk >> 3, pos = chunk & 7;
            cp_async16(sb + (uint32_t)(row * GA_LDB + pos * 4) * 4,
                       Bk + (size_t)row * NN + pos * 4);
        }
        cp_commit();
    };
    auto unit_bases = [&](int u, const float*& Ab, const float*& Bb) {
        int m0 = (u & 127) * 64;
        int ks = u >> 7;
        Ab = adj + (size_t)m0 * NN + (size_t)ks * GA_KSLC;
        Bb = featT + (size_t)ks * GA_KSLC;
    };

    int u = blockIdx.x;                          // < 148 < NUNITS always
    const float *Ab, *Bb, *Abn, *Bbn;
    unit_bases(u, Ab, Bb);
    cpAB(Ab, Bb, 0, 0);
    int stage = 0;

    for (; u < NUNITS; u += NSM) {
        float acc[2][NI][4];
        #pragma unroll
        for (int i = 0; i < 2; i++)
            #pragma unroll
            for (int j = 0; j < NI; j++)
                #pragma unroll
                for (int q = 0; q < 4; q++) acc[i][j][q] = 0.f;

        const bool has_next = (u + NSM < NUNITS);
        if (has_next) unit_bases(u + NSM, Abn, Bbn);

        for (int kt = 0; kt < GA_KT; kt++) {
            CP_WAIT(0);
            __syncthreads();
            if (kt + 1 < GA_KT)      cpAB(Ab,  Bb,  kt + 1, stage ^ 1);
            else if (has_next)       cpAB(Abn, Bbn, 0,      stage ^ 1);

            const float* As = smf + stage * GA_STG;
            const float* Bf = As + GA_ASTG;

            #pragma unroll
            for (int g = 0; g < 4; g++) {
                const int kk = g * 8;
                uint32_t a[2][4], b[NI][2];
                #pragma unroll
                for (int mi = 0; mi < 2; mi++) {
                    int base = (wm + mi * 16 + r) * GA_LDA + kk + c4;
                    a[mi][0] = f2tf32(As[base]);
                    a[mi][1] = f2tf32(As[base + 8 * GA_LDA]);
                    a[mi][2] = f2tf32(As[base + 4]);
                    a[mi][3] = f2tf32(As[base + 8 * GA_LDA + 4]);
                }
                #pragma unroll
                for (int ni = 0; ni < NI; ni++) {
                    float2 v = *(const float2*)(Bf + (wn + ni * 8 + r) * GA_LDB + kk + 2 * c4);
                    b[ni][0] = __float_as_uint(v.x);
                    b[ni][1] = __float_as_uint(v.y);
                }
                #pragma unroll
                for (int mi = 0; mi < 2; mi++)
                    #pragma unroll
                    for (int ni = 0; ni < NI; ni++)
                        mma_tf32(acc[mi][ni], a[mi], b[ni]);
            }
            stage ^= 1;
        }

        // epilogue for unit u (overlaps the next unit's in-flight prologue load)
        {
            int m0 = (u & 127) * 64;
            int ks = u >> 7;
            float* Ydst = Ypart + (size_t)ks * NN * NPAD;
            #pragma unroll
            for (int mi = 0; mi < 2; mi++) {
                #pragma unroll
                for (int h = 0; h < 2; h++) {
                    int row = m0 + wm + mi * 16 + r + h * 8;
                    float* dst = Ydst + (size_t)row * NPAD + wn;
                    #pragma unroll
                    for (int ni = 0; ni < NI; ni++) {
                        int col = ni * 8 + c4 * 2;
                        float2 v;
                        v.x = acc[mi][ni][h * 2 + 0];
                        v.y = acc[mi][ni][h * 2 + 1];
                        *(float2*)(dst + col) = v;
                    }
                }
            }
        }
        Ab = Abn; Bb = Bbn;
    }
}

// ---------------------------------------------------------------------------
// Reduce: Y = sum_{ks} Ypart[ks]  (deterministic fixed-order fp32 adds)
// ---------------------------------------------------------------------------
__global__ __launch_bounds__(256)
void reduce_ypart(const float4* __restrict__ yp, float4* __restrict__ y)
{
    constexpr size_t STRIDE = (size_t)NN * NPAD / 4;
    size_t i = (size_t)blockIdx.x * 256 + threadIdx.x;
    float4 s = yp[i];
    #pragma unroll
    for (int p = 1; p < KSPLIT; p++) {
        float4 v = yp[i + (size_t)p * STRIDE];
        s.x += v.x; s.y += v.y; s.z += v.z; s.w += v.w;
    }
    y[i] = s;
}

// ---------------------------------------------------------------------------
// GEMM_B: h1 = relu(Y @ W1 + b1)  [M=8192, N=1024(HPAD), K=352]
// CTA 128m x 256n, 512 thr = 16 warps (4m x 4n), warp 32x64 (mi=2, ni=8).
// 3-stage cp.async, one barrier per ktile. lda = NPAD = 352.
// ---------------------------------------------------------------------------
constexpr int GB_LDA = 36;
constexpr int GB_LDB = 40;
constexpr int GB_ASTG = 128 * GB_LDA;           // 4608 floats
constexpr int GB_BSTG = 256 * GB_LDB;           // 10240 floats
constexpr int GB_STG  = GB_ASTG + GB_BSTG;      // 14848
constexpr int GB_SMEM = 3 * GB_STG * 4;         // 178176 B
constexpr int GB_KT   = NPAD / 32;              // 11 ktiles

__global__ __launch_bounds__(512, 1)
void gemmB(const float* __restrict__ Yb,
           const float* __restrict__ W1T,
           const float* __restrict__ bias,
           float* __restrict__ C)
{
    extern __shared__ float smf[];
    const uint32_t smb = (uint32_t)__cvta_generic_to_shared(smf);
    const int tid  = threadIdx.x;
    const int lane = tid & 31;
    const int wid  = tid >> 5;
    const int wm   = (wid & 3) * 32;
    const int wn   = (wid >> 2) * 64;
    const int r    = lane >> 2;
    const int c4   = lane & 3;
    const int m0   = blockIdx.y * 128;
    const int n0   = blockIdx.x * 256;

    const float* Abase = Yb  + (size_t)m0 * NPAD;
    const float* Bbase = W1T + (size_t)n0 * NPAD;

    float acc[2][8][4];
    #pragma unroll
    for (int i = 0; i < 2; i++)
        #pragma unroll
        for (int j = 0; j < 8; j++)
            #pragma unroll
            for (int q = 0; q < 4; q++) acc[i][j][q] = 0.f;

    const int row8 = tid >> 3, pos = tid & 7;

    auto cpAB = [&](int kt, int s) {
        const uint32_t sa = smb + (uint32_t)(s * GB_STG) * 4;
        const uint32_t sb = sa + (uint32_t)GB_ASTG * 4;
        const float* Ak = Abase + kt * 32;
        const float* Bk = Bbase + kt * 32;
        #pragma unroll
        for (int c = 0; c < 2; c++) {
            int row = row8 + c * 64;
            cp_async16(sa + (uint32_t)(row * GB_LDA + pos * 4) * 4,
                       Ak + (size_t)row * NPAD + pos * 4);
        }
        #pragma unroll
        for (int c = 0; c < 4; c++) {
            int row = row8 + c * 64;
            cp_async16(sb + (uint32_t)(row * GB_LDB + pos * 4) * 4,
                       Bk + (size_t)row * NPAD + pos * 4);
        }
        cp_commit();
    };

    cpAB(0, 0);
    cpAB(1, 1);

    for (int kt = 0; kt < GB_KT; kt++) {
        if (kt + 1 < GB_KT) { CP_WAIT(1); } else { CP_WAIT(0); }
        __syncthreads();
        if (kt + 2 < GB_KT) cpAB(kt + 2, (kt + 2) % 3);

        const float* As = smf + (kt % 3) * GB_STG;
        const float* Bf = As + GB_ASTG;

        #pragma unroll
        for (int g = 0; g < 4; g++) {
            const int kk = g * 8;
            uint32_t a[2][4], b[8][2];
            #pragma unroll
            for (int mi = 0; mi < 2; mi++) {
                int base = (wm + mi * 16 + r) * GB_LDA + kk + c4;
                a[mi][0] = f2tf32(As[base]);
                a[mi][1] = f2tf32(As[base + 8 * GB_LDA]);
                a[mi][2] = f2tf32(As[base + 4]);
                a[mi][3] = f2tf32(As[base + 8 * GB_LDA + 4]);
            }
            #pragma unroll
            for (int ni = 0; ni < 8; ni++) {
                float2 v = *(const float2*)(Bf + (wn + ni * 8 + r) * GB_LDB + kk + 2 * c4);
                b[ni][0] = __float_as_uint(v.x);
                b[ni][1] = __float_as_uint(v.y);
            }
            #pragma unroll
            for (int mi = 0; mi < 2; mi++)
                #pragma unroll
                for (int ni = 0; ni < 8; ni++)
                    mma_tf32(acc[mi][ni], a[mi], b[ni]);
        }
    }

    #pragma unroll
    for (int mi = 0; mi < 2; mi++) {
        #pragma unroll
        for (int h = 0; h < 2; h++) {
            int row = m0 + wm + mi * 16 + r + h * 8;
            float* dst = C + (size_t)row * HPAD + n0 + wn;
            #pragma unroll
            for (int ni = 0; ni < 8; ni++) {
                int col = ni * 8 + c4 * 2;
                float2 v;
                v.x = fmaxf(acc[mi][ni][h * 2 + 0] + bias[n0 + wn + col],     0.f);
                v.y = fmaxf(acc[mi][ni][h * 2 + 1] + bias[n0 + wn + col + 1], 0.f);
                *(float2*)(dst + col) = v;
            }
        }
    }
}

// ---------------------------------------------------------------------------
// transpose feat [8192, 343] -> featT [352, 8192], RNA, k-permuted, padded.
// ---------------------------------------------------------------------------
__global__ void transpose_feat(const float* __restrict__ in,
                               float* __restrict__ out)
{
    __shared__ float t[32][33];
    int x  = blockIdx.x * 32 + threadIdx.x;
    int y0 = blockIdx.y * 32;
    #pragma unroll
    for (int j = threadIdx.y; j < 32; j += 8)
        t[j][threadIdx.x] = (x < IND) ? in[(size_t)(y0 + j) * IND + x] : 0.f;
    __syncthreads();
    int k  = y0 + threadIdx.x;
    int o  = k & 7;
    int kp = (k & ~7) | ((o < 4) ? (2 * o) : (2 * (o - 4) + 1));
    int n0 = blockIdx.x * 32;
    #pragma unroll
    for (int j = threadIdx.y; j < 32; j += 8)
        out[(size_t)(n0 + j) * NN + kp] = rna_f(t[threadIdx.x][j]);
}

// ---------------------------------------------------------------------------
// transpose W1 [343, 1000] -> W1T [1024, 352], RNA, k-permuted, padded.
// ---------------------------------------------------------------------------
__global__ void transpose_w1(const float* __restrict__ in,
                             float* __restrict__ out)
{
    __shared__ float t[32][33];
    int x  = blockIdx.x * 32 + threadIdx.x;
    int y0 = blockIdx.y * 32;
    #pragma unroll
    for (int j = threadIdx.y; j < 32; j += 8) {
        int k = y0 + j;
        t[j][threadIdx.x] = (x < HIDD && k < IND) ? in[(size_t)k * HIDD + x] : 0.f;
    }
    __syncthreads();
    int k  = y0 + threadIdx.x;
    int o  = k & 7;
    int kp = (k & ~7) | ((o < 4) ? (2 * o) : (2 * (o - 4) + 1));
    int n0 = blockIdx.x * 32;
    #pragma unroll
    for (int j = threadIdx.y; j < 32; j += 8)
        out[(size_t)(n0 + j) * NPAD + kp] = rna_f(t[threadIdx.x][j]);
}

__global__ void pad_bias_kernel(const float* __restrict__ b1, float* __restrict__ b1p) {
    int i = threadIdx.x;
    b1p[i] = (i < HIDD) ? b1[i] : 0.f;
}

// ---------------------------------------------------------------------------
// LayerNorm(1000) + head, one warp per row, float4 loads.
// ---------------------------------------------------------------------------
__global__ __launch_bounds__(256)
void ln_head_kernel(const float* __restrict__ h,
                    const float* __restrict__ gamma,
                    const float* __restrict__ beta,
                    const float* __restrict__ Wm,
                    const float* __restrict__ bm,
                    float* __restrict__ out)
{
    const int row  = blockIdx.x * 8 + threadIdx.y;
    const int lane = threadIdx.x;
    const float4* hr = (const float4*)(h + (size_t)row * HPAD);
    const float4* g4 = (const float4*)gamma;
    const float4* be4 = (const float4*)beta;
    const float4* wm4 = (const float4*)Wm;

    float4 v[8];
    float s = 0.f, ss = 0.f;
    #pragma unroll
    for (int i = 0; i < 8; i++) {
        int idx = lane + 32 * i;
        float4 x = (idx < 250) ? hr[idx] : make_float4(0.f, 0.f, 0.f, 0.f);
        v[i] = x;
        s  += x.x + x.y + x.z + x.w;
        ss += x.x * x.x + x.y * x.y + x.z * x.z + x.w * x.w;
    }
    #pragma unroll
    for (int off = 16; off > 0; off >>= 1) {
        s  += __shfl_xor_sync(0xFFFFFFFF, s,  off);
        ss += __shfl_xor_sync(0xFFFFFFFF, ss, off);
    }
    const float mu   = s * (1.0f / HIDD);
    const float var  = ss * (1.0f / HIDD) - mu * mu;
    const float rinv = rsqrtf(var + EPS);

    float4 acc = make_float4(0.f, 0.f, 0.f, 0.f);
    #pragma unroll
    for (int i = 0; i < 8; i++) {
        int idx = lane + 32 * i;
        if (idx < 250) {
            float4 g = g4[idx], be = be4[idx];
            float xn0 = (v[i].x - mu) * rinv * g.x + be.x;
            float xn1 = (v[i].y - mu) * rinv * g.y + be.y;
            float xn2 = (v[i].z - mu) * rinv * g.z + be.z;
            float xn3 = (v[i].w - mu) * rinv * g.w + be.w;
            float4 w0 = wm4[idx * 4 + 0];
            float4 w1 = wm4[idx * 4 + 1];
            float4 w2 = wm4[idx * 4 + 2];
            float4 w3 = wm4[idx * 4 + 3];
            acc.x = fmaf(xn0, w0.x, fmaf(xn1, w1.x, fmaf(xn2, w2.x, fmaf(xn3, w3.x, acc.x))));
            acc.y = fmaf(xn0, w0.y, fmaf(xn1, w1.y, fmaf(xn2, w2.y, fmaf(xn3, w3.y, acc.y))));
            acc.z = fmaf(xn0, w0.z, fmaf(xn1, w1.z, fmaf(xn2, w2.z, fmaf(xn3, w3.z, acc.z))));
            acc.w = fmaf(xn0, w0.w, fmaf(xn1, w1.w, fmaf(xn2, w2.w, fmaf(xn3, w3.w, acc.w))));
        }
    }
    #pragma unroll
    for (int off = 16; off > 0; off >>= 1) {
        acc.x += __shfl_xor_sync(0xFFFFFFFF, acc.x, off);
        acc.y += __shfl_xor_sync(0xFFFFFFFF, acc.y, off);
        acc.z += __shfl_xor_sync(0xFFFFFFFF, acc.z, off);
        acc.w += __shfl_xor_sync(0xFFFFFFFF, acc.w, off);
    }
    if (lane == 0) {
        float4 b = *(const float4*)bm;
        float4 o;
        o.x = acc.x + b.x; o.y = acc.y + b.y;
        o.z = acc.z + b.z; o.w = acc.w + b.w;
        *(float4*)(out + (size_t)row * OUTD) = o;
    }
}

// ---------------------------------------------------------------------------
extern "C" void kernel_launch(void* const* d_in, const int* in_sizes, int n_in,
                              void* d_out, int out_size)
{
    const float* adj   = (const float*)d_in[0];
    const float* feat  = (const float*)d_in[1];
    const float* W1    = (const float*)d_in[2];
    const float* b1    = (const float*)d_in[3];
    const float* gamma = (const float*)d_in[4];
    const float* beta  = (const float*)d_in[5];
    const float* Wm    = (const float*)d_in[6];
    const float* bm    = (const float*)d_in[7];
    float* out = (float*)d_out;

    float *featT, *Ypart, *Yb, *W1T, *h1, *b1p;
    cudaGetSymbolAddress((void**)&featT, g_featT);
    cudaGetSymbolAddress((void**)&Ypart, g_Ypart);
    cudaGetSymbolAddress((void**)&Yb,    g_Y);
    cudaGetSymbolAddress((void**)&W1T,   g_W1T);
    cudaGetSymbolAddress((void**)&h1,    g_h1);
    cudaGetSymbolAddress((void**)&b1p,   g_b1p);

    cudaFuncSetAttribute(gemmA_persist, cudaFuncAttributeMaxDynamicSharedMemorySize, GA_SMEM);
    cudaFuncSetAttribute(gemmB,         cudaFuncAttributeMaxDynamicSharedMemorySize, GB_SMEM);

    // prep: featT, W1T, padded bias
    {
        dim3 block(32, 8);
        dim3 gridF(NPAD / 32, NN / 32);
        transpose_feat<<<gridF, block>>>(feat, featT);
        dim3 gridW(HPAD / 32, NPAD / 32);
        transpose_w1<<<gridW, block>>>(W1, W1T);
        pad_bias_kernel<<<1, HPAD>>>(b1, b1p);
    }

    // GEMM_A: persistent 148 CTAs over 1024 split-K units (256 thr, 8 warps)
    gemmA_persist<<<NSM, 256, GA_SMEM>>>(adj, featT, Ypart);

    // deterministic reduction: Y = sum(Ypart)
    reduce_ypart<<<(NN * NPAD / 4) / 256, 256>>>((const float4*)Ypart, (float4*)Yb);

    // GEMM_B: h1 = relu(Y @ W1 + b1)
    {
        dim3 grid(HPAD / 256, NN / 128);
        gemmB<<<grid, 512, GB_SMEM>>>(Yb, W1T, b1p, h1);
    }

    // LayerNorm + head
    {
        dim3 block(32, 8);
        ln_head_kernel<<<NN / 8, block>>>(h1, gamma, beta, Wm, bm, out);
    }
}